// round 3
// baseline (speedup 1.0000x reference)
#include <cuda_runtime.h>
#include <math.h>

#define B_   16
#define C_   256
#define H_   64
#define HW_  4096
#define L_   40
#define TD_  768
#define EMB_ 392
#define NC_  8

typedef unsigned long long u64;

// ---- scratch (no cudaMalloc allowed) ----
__device__ float g_bufA[B_*C_*HW_];   // 67 MB
__device__ float g_bufB[B_*C_*HW_];   // 67 MB
__device__ float g_g[B_*HW_];
__device__ float g_bmax[B_*HW_];
__device__ float g_S[B_*C_*9];
__device__ float g_yc[B_*NC_];
__device__ float g_xc[B_*NC_];
__device__ float g_sy[B_*NC_];

__device__ __forceinline__ float sigmf(float x){ return 1.f/(1.f+expf(-x)); }

// ---- packed f32x2 helpers (FFMA2: ptxas never auto-emits, must be explicit PTX) ----
__device__ __forceinline__ u64 bcast2(float x){
    u64 r; unsigned xi = __float_as_uint(x);
    asm("mov.b64 %0, {%1, %2};" : "=l"(r) : "r"(xi), "r"(xi));
    return r;
}
__device__ __forceinline__ void ffma2(u64 &d, u64 a, u64 b){
    asm("fma.rn.f32x2 %0, %1, %2, %3;" : "=l"(d) : "l"(a), "l"(b), "l"(d));
}
__device__ __forceinline__ void unpack2(u64 d, float &lo, float &hi){
    unsigned l, h;
    asm("mov.b64 {%0, %1}, %2;" : "=r"(l), "=r"(h) : "l"(d));
    lo = __uint_as_float(l); hi = __uint_as_float(h);
}

// ---------------- K1: language path -> yc/xc ----------------
__global__ void k_lang(const float* __restrict__ flang, const int* __restrict__ wmask,
                       const float* __restrict__ W1, const float* __restrict__ b1,
                       const float* __restrict__ W2, const float* __restrict__ b2)
{
    __shared__ float incs[L_];
    __shared__ float favg[TD_];
    __shared__ float e1s[EMB_];
    __shared__ float mapv[16];
    __shared__ float sinv;
    int b = blockIdx.x, tid = threadIdx.x;
    if (tid == 0){
        float cs[L_]; float c = 0.f;
        for (int l = 0; l < L_; l++){ c += (float)wmask[b*L_+l]; cs[l] = c; }
        float tot = c, s = 0.f;
        for (int l = 0; l < L_; l++){
            float m = (float)wmask[b*L_+l];
            float v = (cs[l] > 1.f && cs[l] < tot) ? m : 0.f;
            incs[l] = v; s += v;
        }
        sinv = 1.f/s;
    }
    __syncthreads();
    for (int d = tid; d < TD_; d += 256){
        float a = 0.f;
        for (int l = 0; l < L_; l++) a += flang[((size_t)b*L_+l)*TD_+d]*incs[l];
        favg[d] = a*sinv;
    }
    __syncthreads();
    for (int j = tid; j < EMB_; j += 256){
        float a = b1[j];
        const float* w = W1 + (size_t)j*TD_;
        for (int d = 0; d < TD_; d++) a = fmaf(favg[d], w[d], a);
        e1s[j] = a;
    }
    __syncthreads();
    if (tid < 16){
        float a = b2[tid];
        const float* w = W2 + (size_t)tid*EMB_;
        for (int j = 0; j < EMB_; j++) a = fmaf(e1s[j], w[j], a);
        mapv[tid] = sigmf(a);
    }
    __syncthreads();
    if (tid < NC_){
        float y = mapv[2*tid]   * (float)H_;
        float x = mapv[2*tid+1] * (float)H_;
        g_yc[b*NC_+tid] = (float)(int)y;   // trunc like astype(int32)
        g_xc[b*NC_+tid] = (float)(int)x;
    }
}

// ---------------- K2: 9 shifted window sums S[b,c,dy,dx] ----------------
__global__ void k_ssum(const float* __restrict__ img)
{
    int bc = blockIdx.x;            // b*C + c
    int tid = threadIdx.x;
    const float* p = img + (size_t)bc*HW_;
    float acc[9];
    #pragma unroll
    for (int j = 0; j < 9; j++) acc[j] = 0.f;
    for (int i = tid; i < HW_; i += 128){
        int h = i >> 6, w = i & 63;
        float v = p[i];
        #pragma unroll
        for (int dy = 0; dy < 3; dy++){
            bool oy = (h - dy) >= 0 && (h - dy) <= 61;
            #pragma unroll
            for (int dx = 0; dx < 3; dx++){
                bool ox = (w - dx) >= 0 && (w - dx) <= 61;
                if (oy && ox) acc[dy*3+dx] += v;
            }
        }
    }
    __shared__ float red[9][128];
    #pragma unroll
    for (int j = 0; j < 9; j++) red[j][tid] = acc[j];
    __syncthreads();
    for (int off = 64; off > 0; off >>= 1){
        if (tid < off){
            #pragma unroll
            for (int j = 0; j < 9; j++) red[j][tid] += red[j][tid+off];
        }
        __syncthreads();
    }
    if (tid < 9) g_S[(size_t)bc*9 + tid] = red[tid][0];
}

// ---------------- K3: sigma_y[b,nc] ----------------
__global__ void k_sigma(const float* __restrict__ Ws, const float* __restrict__ bs,
                        const float* __restrict__ sigma_w)
{
    int bn = blockIdx.x; int b = bn >> 3; int nc = bn & 7;
    int tid = threadIdx.x;
    const float* w = Ws  + (size_t)nc*C_*9;
    const float* s = g_S + (size_t)b*C_*9;
    float a = 0.f;
    for (int i = tid; i < C_*9; i += 128) a = fmaf(w[i], s[i], a);
    __shared__ float red[128];
    red[tid] = a; __syncthreads();
    for (int off = 64; off > 0; off >>= 1){
        if (tid < off) red[tid] += red[tid+off];
        __syncthreads();
    }
    if (tid == 0){
        float mean = red[0]*(1.f/3844.f) + bs[nc];
        g_sy[bn] = sigma_w[0]*(float)H_*sigmf(mean);
    }
}

// ---------------- K4: gaussian weights -> gamma/beta -> g, bmax ----------------
__global__ void k_gbmax(const float* __restrict__ Wg, const float* __restrict__ sg, const float* __restrict__ bg,
                        const float* __restrict__ Wb, const float* __restrict__ sb, const float* __restrict__ bb,
                        const float* __restrict__ sigma_w)
{
    int blk = blockIdx.x; int b = blk >> 4; int chunk = blk & 15;
    int tid = threadIdx.x;
    __shared__ float syc[8], sxc[8], ssy[8], swg[64], swb[64], ssg[8], sbgs[8], ssb[8], sbbs[8];
    if (tid < 8){
        syc[tid] = g_yc[b*8+tid]; sxc[tid] = g_xc[b*8+tid]; ssy[tid] = g_sy[b*8+tid];
        ssg[tid] = sg[tid]; sbgs[tid] = bg[tid]; ssb[tid] = sb[tid]; sbbs[tid] = bb[tid];
    }
    if (tid < 64){ swg[tid] = Wg[tid]; swb[tid] = Wb[tid]; }
    __syncthreads();
    float sx = sigma_w[0]*(float)H_;
    float inv2sx2 = 1.f/(2.f*sx*sx);
    int p = chunk*256 + tid;
    float fh = (float)(p >> 6), fw = (float)(p & 63);
    float wv[8];
    #pragma unroll
    for (int i = 0; i < 8; i++){
        float dy = fh - syc[i], dx = fw - sxc[i];
        float sy = ssy[i];
        wv[i] = expf(-(dy*dy/(2.f*sy*sy) + dx*dx*inv2sx2));
    }
    float gsum = 0.f, bmx = -1e30f;
    #pragma unroll
    for (int j = 0; j < 8; j++){
        float ag = 0.f, ab = 0.f;
        #pragma unroll
        for (int i = 0; i < 8; i++){
            ag = fmaf(swg[j*8+i], wv[i], ag);
            ab = fmaf(swb[j*8+i], wv[i], ab);
        }
        float yg = fmaf(ag, ssg[j], sbgs[j]);
        gsum += tanhf(yg*sigmf(yg));
        float yb = fmaf(ab, ssb[j], sbbs[j]);
        bmx = fmaxf(bmx, tanhf(yb*sigmf(yb)));
    }
    g_g[(size_t)b*HW_+p]    = gsum*0.125f;
    g_bmax[(size_t)b*HW_+p] = bmx;
}

// ---- shared mainloop body: rank-1 updates with packed FFMA2 ----
// acc[i][j] holds output pair (row ty*8+i, cols tx*8+2j, +2j+1)
#define COMPUTE_TILE(As_cur, Bs_cur)                                           \
    _Pragma("unroll")                                                          \
    for (int kk = 0; kk < 8; kk++){                                            \
        float a[8];                                                            \
        *(float4*)(a)   = *(const float4*)(&As_cur[kk][ty*8]);                 \
        *(float4*)(a+4) = *(const float4*)(&As_cur[kk][ty*8+4]);               \
        ulonglong2 q0 = *(const ulonglong2*)(&Bs_cur[kk][tx*8]);               \
        ulonglong2 q1 = *(const ulonglong2*)(&Bs_cur[kk][tx*8+4]);             \
        u64 b2[4]; b2[0]=q0.x; b2[1]=q0.y; b2[2]=q1.x; b2[3]=q1.y;             \
        _Pragma("unroll")                                                      \
        for (int i = 0; i < 8; i++){                                           \
            u64 ap = bcast2(a[i]);                                             \
            ffma2(acc[i][0], ap, b2[0]);                                       \
            ffma2(acc[i][1], ap, b2[1]);                                       \
            ffma2(acc[i][2], ap, b2[2]);                                       \
            ffma2(acc[i][3], ap, b2[3]);                                       \
        }                                                                      \
    }

// ---------------- 128x128x8 SGEMM (double-buffered, FFMA2) with fused epilogues
// EPI 0: map_visu path: y=acc*s+b; silu; tanh; out = g*t + bmax
// EPI 1: cbs: y=acc*s+b; out = silu(y)
// EPI 2: final: y=acc+b; out = (1+aw)*img + (1-aw)*y
template<int EPI>
__global__ __launch_bounds__(256) void k_gemm(
    const float* __restrict__ A, const float* __restrict__ X, float* __restrict__ Y,
    const float* __restrict__ scale, const float* __restrict__ bias,
    const float* __restrict__ img, const float* __restrict__ awp)
{
    __shared__ float As[2][8][128];
    __shared__ float Bs[2][8][128];
    int b  = blockIdx.z;
    int m0 = blockIdx.y*128, n0 = blockIdx.x*128;
    const float* Xb = X + (size_t)b*C_*HW_;
    float* Yb = Y + (size_t)b*C_*HW_;
    int tid = threadIdx.x;
    int tx = tid & 15, ty = tid >> 4;
    int arow = tid >> 1, acol = (tid & 1)*4;
    int brow = tid >> 5, bcol = (tid & 31)*4;

    u64 acc[8][4];
    #pragma unroll
    for (int i = 0; i < 8; i++)
        #pragma unroll
        for (int j = 0; j < 4; j++) acc[i][j] = 0ull;

    // prologue: tile 0
    {
        float4 av = *(const float4*)(A  + (size_t)(m0+arow)*C_  + acol);
        float4 bv = *(const float4*)(Xb + (size_t)brow*HW_ + n0 + bcol);
        As[0][acol+0][arow] = av.x; As[0][acol+1][arow] = av.y;
        As[0][acol+2][arow] = av.z; As[0][acol+3][arow] = av.w;
        *(float4*)(&Bs[0][brow][bcol]) = bv;
    }
    __syncthreads();

    const int NIT = C_/8;
    for (int it = 0; it < NIT; it++){
        int cur = it & 1, nxt = cur ^ 1;
        float4 av, bv;
        if (it+1 < NIT){
            int k0 = (it+1)*8;
            av = *(const float4*)(A  + (size_t)(m0+arow)*C_  + k0 + acol);
            bv = *(const float4*)(Xb + (size_t)(k0+brow)*HW_ + n0 + bcol);
        }
        COMPUTE_TILE(As[cur], Bs[cur])
        if (it+1 < NIT){
            As[nxt][acol+0][arow] = av.x; As[nxt][acol+1][arow] = av.y;
            As[nxt][acol+2][arow] = av.z; As[nxt][acol+3][arow] = av.w;
            *(float4*)(&Bs[nxt][brow][bcol]) = bv;
        }
        __syncthreads();
    }

    float aw = 0.f;
    if (EPI == 2) aw = tanhf(awp[0]);
    float gn[8], bn[8];
    if (EPI == 0){
        #pragma unroll
        for (int j = 0; j < 8; j++){
            int n = n0 + tx*8 + j;
            gn[j] = g_g[(size_t)b*HW_+n];
            bn[j] = g_bmax[(size_t)b*HW_+n];
        }
    }
    #pragma unroll
    for (int i = 0; i < 8; i++){
        int m = m0 + ty*8 + i;
        float sm = (EPI == 2) ? 1.f : scale[m];
        float bm = bias[m];
        float o[8];
        #pragma unroll
        for (int jj = 0; jj < 4; jj++){
            float v0, v1; unpack2(acc[i][jj], v0, v1);
            float y0 = fmaf(v0, sm, bm);
            float y1 = fmaf(v1, sm, bm);
            if (EPI == 0){
                float s0 = y0*sigmf(y0), s1 = y1*sigmf(y1);
                o[2*jj]   = fmaf(gn[2*jj],   tanhf(s0), bn[2*jj]);
                o[2*jj+1] = fmaf(gn[2*jj+1], tanhf(s1), bn[2*jj+1]);
            } else if (EPI == 1){
                o[2*jj]   = y0*sigmf(y0);
                o[2*jj+1] = y1*sigmf(y1);
            } else {
                int n = n0 + tx*8 + 2*jj;
                float i0 = img[((size_t)b*C_ + m)*HW_ + n];
                float i1 = img[((size_t)b*C_ + m)*HW_ + n + 1];
                o[2*jj]   = (1.f+aw)*i0 + (1.f-aw)*y0;
                o[2*jj+1] = (1.f+aw)*i1 + (1.f-aw)*y1;
            }
        }
        float* dst = Yb + (size_t)m*HW_ + n0 + tx*8;
        *(float4*)dst     = make_float4(o[0], o[1], o[2], o[3]);
        *(float4*)(dst+4) = make_float4(o[4], o[5], o[6], o[7]);
    }
}

// ---------------- implicit-GEMM 3x3 conv (pad=1), K=2304, double-buffered FFMA2, cbs epilogue
__device__ __forceinline__ void conv_loadB(const float* __restrict__ Xb, int k0,
                                           int brow, int bcol, int n0, float* bvv)
{
    int kk = k0 + brow;
    int c  = kk/9; int r = kk - c*9;
    int ry = r/3 - 1;
    int rx = (r - (r/3)*3) - 1;
    #pragma unroll
    for (int j = 0; j < 4; j++){
        int n = n0 + bcol + j;
        int h = (n >> 6) + ry, w = (n & 63) + rx;
        bool ok = (unsigned)h < 64u && (unsigned)w < 64u;
        bvv[j] = ok ? Xb[(size_t)c*HW_ + (h << 6) + w] : 0.f;
    }
}

__global__ __launch_bounds__(256) void k_conv3(
    const float* __restrict__ A,   // [256][2304] = Wf2
    const float* __restrict__ X, float* __restrict__ Y,
    const float* __restrict__ scale, const float* __restrict__ bias)
{
    __shared__ float As[2][8][128];
    __shared__ float Bs[2][8][128];
    int b  = blockIdx.z;
    int m0 = blockIdx.y*128, n0 = blockIdx.x*128;
    const float* Xb = X + (size_t)b*C_*HW_;
    float* Yb = Y + (size_t)b*C_*HW_;
    int tid = threadIdx.x;
    int tx = tid & 15, ty = tid >> 4;
    int arow = tid >> 1, acol = (tid & 1)*4;
    int brow = tid >> 5, bcol = (tid & 31)*4;

    u64 acc[8][4];
    #pragma unroll
    for (int i = 0; i < 8; i++)
        #pragma unroll
        for (int j = 0; j < 4; j++) acc[i][j] = 0ull;

    // prologue
    {
        float4 av = *(const float4*)(A + (size_t)(m0+arow)*2304 + acol);
        float bvv[4];
        conv_loadB(Xb, 0, brow, bcol, n0, bvv);
        As[0][acol+0][arow] = av.x; As[0][acol+1][arow] = av.y;
        As[0][acol+2][arow] = av.z; As[0][acol+3][arow] = av.w;
        Bs[0][brow][bcol+0] = bvv[0]; Bs[0][brow][bcol+1] = bvv[1];
        Bs[0][brow][bcol+2] = bvv[2]; Bs[0][brow][bcol+3] = bvv[3];
    }
    __syncthreads();

    const int NIT = 2304/8;
    for (int it = 0; it < NIT; it++){
        int cur = it & 1, nxt = cur ^ 1;
        float4 av; float bvv[4];
        if (it+1 < NIT){
            int k0 = (it+1)*8;
            av = *(const float4*)(A + (size_t)(m0+arow)*2304 + k0 + acol);
            conv_loadB(Xb, k0, brow, bcol, n0, bvv);
        }
        COMPUTE_TILE(As[cur], Bs[cur])
        if (it+1 < NIT){
            As[nxt][acol+0][arow] = av.x; As[nxt][acol+1][arow] = av.y;
            As[nxt][acol+2][arow] = av.z; As[nxt][acol+3][arow] = av.w;
            Bs[nxt][brow][bcol+0] = bvv[0]; Bs[nxt][brow][bcol+1] = bvv[1];
            Bs[nxt][brow][bcol+2] = bvv[2]; Bs[nxt][brow][bcol+3] = bvv[3];
        }
        __syncthreads();
    }

    #pragma unroll
    for (int i = 0; i < 8; i++){
        int m = m0 + ty*8 + i;
        float sm = scale[m], bm = bias[m];
        float o[8];
        #pragma unroll
        for (int jj = 0; jj < 4; jj++){
            float v0, v1; unpack2(acc[i][jj], v0, v1);
            float y0 = fmaf(v0, sm, bm);
            float y1 = fmaf(v1, sm, bm);
            o[2*jj]   = y0*sigmf(y0);
            o[2*jj+1] = y1*sigmf(y1);
        }
        float* dst = Yb + (size_t)m*HW_ + n0 + tx*8;
        *(float4*)dst     = make_float4(o[0], o[1], o[2], o[3]);
        *(float4*)(dst+4) = make_float4(o[4], o[5], o[6], o[7]);
    }
}

// ---------------- channelwise L2 norm ----------------
__global__ void k_l2norm(const float* __restrict__ X, float* __restrict__ Y)
{
    int q = blockIdx.x*128 + threadIdx.x;   // < B*HW
    int b = q >> 12, p = q & 4095;
    const float* xp = X + (size_t)b*C_*HW_ + p;
    float a0 = 0.f, a1 = 0.f, a2 = 0.f, a3 = 0.f;
    #pragma unroll 8
    for (int c = 0; c < C_; c += 4){
        float v0 = xp[(size_t)c*HW_];
        float v1 = xp[(size_t)(c+1)*HW_];
        float v2 = xp[(size_t)(c+2)*HW_];
        float v3 = xp[(size_t)(c+3)*HW_];
        a0 = fmaf(v0, v0, a0); a1 = fmaf(v1, v1, a1);
        a2 = fmaf(v2, v2, a2); a3 = fmaf(v3, v3, a3);
    }
    float n = sqrtf((a0+a1)+(a2+a3));
    float inv = 1.f/fmaxf(n, 1e-12f);
    float* yp = Y + (size_t)b*C_*HW_ + p;
    #pragma unroll 8
    for (int c = 0; c < C_; c++) yp[(size_t)c*HW_] = xp[(size_t)c*HW_]*inv;
}

extern "C" void kernel_launch(void* const* d_in, const int* in_sizes, int n_in,
                              void* d_out, int out_size)
{
    const float* img    = (const float*)d_in[0];
    const float* flang  = (const float*)d_in[1];
    const int*   wmask  = (const int*)  d_in[2];
    const float* sigw   = (const float*)d_in[3];
    const float* W1 = (const float*)d_in[4];  const float* b1 = (const float*)d_in[5];
    const float* W2 = (const float*)d_in[6];  const float* b2 = (const float*)d_in[7];
    const float* Wv = (const float*)d_in[8];  const float* sv = (const float*)d_in[9];  const float* bv = (const float*)d_in[10];
    const float* Wg = (const float*)d_in[11]; const float* sg = (const float*)d_in[12]; const float* bg = (const float*)d_in[13];
    const float* Wb = (const float*)d_in[14]; const float* sb = (const float*)d_in[15]; const float* bb = (const float*)d_in[16];
    const float* Wf1 = (const float*)d_in[17]; const float* sf1 = (const float*)d_in[18]; const float* bf1 = (const float*)d_in[19];
    const float* Wf2 = (const float*)d_in[20]; const float* sf2 = (const float*)d_in[21]; const float* bf2 = (const float*)d_in[22];
    const float* Wf3 = (const float*)d_in[23]; const float* bf3 = (const float*)d_in[24];
    const float* Ws  = (const float*)d_in[25]; const float* bs  = (const float*)d_in[26];
    const float* awp = (const float*)d_in[27];

    float* bufA; cudaGetSymbolAddress((void**)&bufA, g_bufA);
    float* bufB; cudaGetSymbolAddress((void**)&bufB, g_bufB);
    float* outp = (float*)d_out;

    // small path
    k_lang <<<16, 256>>>(flang, wmask, W1, b1, W2, b2);
    k_ssum <<<B_*C_, 128>>>(img);
    k_sigma<<<B_*NC_, 128>>>(Ws, bs, sigw);
    k_gbmax<<<B_*16, 256>>>(Wg, sg, bg, Wb, sb, bb, sigw);

    dim3 gg(HW_/128, C_/128, B_);
    // map_visu + g*t+bmax fused
    k_gemm<0><<<gg, 256>>>(Wv, img, bufA, sv, bv, nullptr, nullptr);
    k_l2norm<<<B_*HW_/128, 128>>>(bufA, bufB);
    // Wf1 cbs
    k_gemm<1><<<gg, 256>>>(Wf1, bufB, bufA, sf1, bf1, nullptr, nullptr);
    // Wf2 3x3 cbs
    k_conv3 <<<gg, 256>>>(Wf2, bufA, bufB, sf2, bf2);
    // Wf3 + residual
    k_gemm<2><<<gg, 256>>>(Wf3, bufB, bufA, nullptr, bf3, img, awp);
    // final l2norm -> out
    k_l2norm<<<B_*HW_/128, 128>>>(bufA, outp);
}

// round 5
// speedup vs baseline: 1.9264x; 1.9264x over previous
#include <cuda_runtime.h>
#include <cuda_bf16.h>
#include <math.h>

#define B_   16
#define C_   256
#define H_   64
#define HW_  4096
#define L_   40
#define TD_  768
#define EMB_ 392
#define NC_  8

typedef unsigned int u32;
typedef unsigned short u16;

// ---- scratch (no cudaMalloc allowed) ----
__device__ float g_bufA[B_*C_*HW_];
__device__ float g_bufB[B_*C_*HW_];
__device__ float g_g[B_*HW_];
__device__ float g_bmax[B_*HW_];
__device__ float g_S[B_*C_*9];
__device__ float g_yc[B_*NC_];
__device__ float g_xc[B_*NC_];
__device__ float g_sy[B_*NC_];
// conv weights, split bf16, k reordered k = r*256 + c
__device__ __align__(16) u16 g_Cwh[256*2304];
__device__ __align__(16) u16 g_Cwl[256*2304];
// 1x1 weights, split bf16: [0]=Wv hi,[1]=Wv lo,[2]=Wf1 hi,[3]=Wf1 lo,[4]=Wf3 hi,[5]=Wf3 lo
__device__ __align__(16) u16 g_P[6][256*256];

__device__ __forceinline__ float sigmf(float x){ return 1.f/(1.f+expf(-x)); }
__device__ __forceinline__ u16 f2bf(float x){
    __nv_bfloat16 h = __float2bfloat16_rn(x);
    return *reinterpret_cast<u16*>(&h);
}
__device__ __forceinline__ float bf2f(u16 u){
    __nv_bfloat16 h; *reinterpret_cast<u16*>(&h) = u;
    return __bfloat162float(h);
}

// ---------------- K1: language path -> yc/xc ----------------
__global__ void k_lang(const float* __restrict__ flang, const int* __restrict__ wmask,
                       const float* __restrict__ W1, const float* __restrict__ b1,
                       const float* __restrict__ W2, const float* __restrict__ b2)
{
    __shared__ float incs[L_];
    __shared__ float favg[TD_];
    __shared__ float e1s[EMB_];
    __shared__ float mapv[16];
    __shared__ float sinv;
    int b = blockIdx.x, tid = threadIdx.x;
    if (tid == 0){
        float cs[L_]; float c = 0.f;
        for (int l = 0; l < L_; l++){ c += (float)wmask[b*L_+l]; cs[l] = c; }
        float tot = c, s = 0.f;
        for (int l = 0; l < L_; l++){
            float m = (float)wmask[b*L_+l];
            float v = (cs[l] > 1.f && cs[l] < tot) ? m : 0.f;
            incs[l] = v; s += v;
        }
        sinv = 1.f/s;
    }
    __syncthreads();
    for (int d = tid; d < TD_; d += 256){
        float a = 0.f;
        for (int l = 0; l < L_; l++) a += flang[((size_t)b*L_+l)*TD_+d]*incs[l];
        favg[d] = a*sinv;
    }
    __syncthreads();
    for (int j = tid; j < EMB_; j += 256){
        float a = b1[j];
        const float* w = W1 + (size_t)j*TD_;
        for (int d = 0; d < TD_; d++) a = fmaf(favg[d], w[d], a);
        e1s[j] = a;
    }
    __syncthreads();
    if (tid < 16){
        float a = b2[tid];
        const float* w = W2 + (size_t)tid*EMB_;
        for (int j = 0; j < EMB_; j++) a = fmaf(e1s[j], w[j], a);
        mapv[tid] = sigmf(a);
    }
    __syncthreads();
    if (tid < NC_){
        float y = mapv[2*tid]   * (float)H_;
        float x = mapv[2*tid+1] * (float)H_;
        g_yc[b*NC_+tid] = (float)(int)y;
        g_xc[b*NC_+tid] = (float)(int)x;
    }
}

// ---------------- K2: 9 shifted window sums ----------------
__global__ void k_ssum(const float* __restrict__ img)
{
    int bc = blockIdx.x;
    int tid = threadIdx.x;
    const float* p = img + (size_t)bc*HW_;
    float acc[9];
    #pragma unroll
    for (int j = 0; j < 9; j++) acc[j] = 0.f;
    for (int i = tid; i < HW_; i += 128){
        int h = i >> 6, w = i & 63;
        float v = p[i];
        #pragma unroll
        for (int dy = 0; dy < 3; dy++){
            bool oy = (h - dy) >= 0 && (h - dy) <= 61;
            #pragma unroll
            for (int dx = 0; dx < 3; dx++){
                bool ox = (w - dx) >= 0 && (w - dx) <= 61;
                if (oy && ox) acc[dy*3+dx] += v;
            }
        }
    }
    __shared__ float red[9][128];
    #pragma unroll
    for (int j = 0; j < 9; j++) red[j][tid] = acc[j];
    __syncthreads();
    for (int off = 64; off > 0; off >>= 1){
        if (tid < off){
            #pragma unroll
            for (int j = 0; j < 9; j++) red[j][tid] += red[j][tid+off];
        }
        __syncthreads();
    }
    if (tid < 9) g_S[(size_t)bc*9 + tid] = red[tid][0];
}

// ---------------- K3: sigma_y ----------------
__global__ void k_sigma(const float* __restrict__ Ws, const float* __restrict__ bs,
                        const float* __restrict__ sigma_w)
{
    int bn = blockIdx.x; int b = bn >> 3; int nc = bn & 7;
    int tid = threadIdx.x;
    const float* w = Ws  + (size_t)nc*C_*9;
    const float* s = g_S + (size_t)b*C_*9;
    float a = 0.f;
    for (int i = tid; i < C_*9; i += 128) a = fmaf(w[i], s[i], a);
    __shared__ float red[128];
    red[tid] = a; __syncthreads();
    for (int off = 64; off > 0; off >>= 1){
        if (tid < off) red[tid] += red[tid+off];
        __syncthreads();
    }
    if (tid == 0){
        float mean = red[0]*(1.f/3844.f) + bs[nc];
        g_sy[bn] = sigma_w[0]*(float)H_*sigmf(mean);
    }
}

// ---------------- K4: gaussians -> g, bmax ----------------
__global__ void k_gbmax(const float* __restrict__ Wg, const float* __restrict__ sg, const float* __restrict__ bg,
                        const float* __restrict__ Wb, const float* __restrict__ sb, const float* __restrict__ bb,
                        const float* __restrict__ sigma_w)
{
    int blk = blockIdx.x; int b = blk >> 4; int chunk = blk & 15;
    int tid = threadIdx.x;
    __shared__ float syc[8], sxc[8], ssy[8], swg[64], swb[64], ssg[8], sbgs[8], ssb[8], sbbs[8];
    if (tid < 8){
        syc[tid] = g_yc[b*8+tid]; sxc[tid] = g_xc[b*8+tid]; ssy[tid] = g_sy[b*8+tid];
        ssg[tid] = sg[tid]; sbgs[tid] = bg[tid]; ssb[tid] = sb[tid]; sbbs[tid] = bb[tid];
    }
    if (tid < 64){ swg[tid] = Wg[tid]; swb[tid] = Wb[tid]; }
    __syncthreads();
    float sx = sigma_w[0]*(float)H_;
    float inv2sx2 = 1.f/(2.f*sx*sx);
    int p = chunk*256 + tid;
    float fh = (float)(p >> 6), fw = (float)(p & 63);
    float wv[8];
    #pragma unroll
    for (int i = 0; i < 8; i++){
        float dy = fh - syc[i], dx = fw - sxc[i];
        float sy = ssy[i];
        wv[i] = expf(-(dy*dy/(2.f*sy*sy) + dx*dx*inv2sx2));
    }
    float gsum = 0.f, bmx = -1e30f;
    #pragma unroll
    for (int j = 0; j < 8; j++){
        float ag = 0.f, ab = 0.f;
        #pragma unroll
        for (int i = 0; i < 8; i++){
            ag = fmaf(swg[j*8+i], wv[i], ag);
            ab = fmaf(swb[j*8+i], wv[i], ab);
        }
        float yg = fmaf(ag, ssg[j], sbgs[j]);
        gsum += tanhf(yg*sigmf(yg));
        float yb = fmaf(ab, ssb[j], sbbs[j]);
        bmx = fmaxf(bmx, tanhf(yb*sigmf(yb)));
    }
    g_g[(size_t)b*HW_+p]    = gsum*0.125f;
    g_bmax[(size_t)b*HW_+p] = bmx;
}

// ---------------- weight prep ----------------
// conv: reorder k = r*256 + c, split to bf16 hi/lo
__global__ void k_prepW(const float* __restrict__ W)
{
    int idx = blockIdx.x*256 + threadIdx.x;
    if (idx >= 256*2304) return;
    int m = idx / 2304;
    int k = idx - m*2304;
    int r = k >> 8;
    int c = k & 255;
    float v = W[(size_t)m*2304 + c*9 + r];
    u16 h = f2bf(v);
    g_Cwh[idx] = h;
    g_Cwl[idx] = f2bf(v - bf2f(h));
}
// 1x1: straight split
__global__ void k_prep1(const float* __restrict__ W, int slot)
{
    int idx = blockIdx.x*256 + threadIdx.x;
    if (idx >= 256*256) return;
    float v = W[idx];
    u16 h = f2bf(v);
    g_P[slot][idx]   = h;
    g_P[slot+1][idx] = f2bf(v - bf2f(h));
}

// ================== warp-MMA GEMM/conv (mma.sync m16n8k16 bf16, split x3) ==================
// CTA: 256 thr = 8 warps (4x2), tile 128(M) x 64(N = one image row), K chunks of 64.
// smem K-major rows of 128B with SW128 swizzle.

#define SWZ(row, kb) ((row)*128 + ((kb) ^ (((row)&7)<<4)))
#define OFF_AH 0
#define OFF_AL 16384
#define OFF_BH 32768
#define OFF_BL 40960

__device__ __forceinline__ u32 smem_u32(const void* p){
    u32 a;
    asm("{ .reg .u64 t; cvta.to.shared.u64 t, %1; cvt.u32.u64 %0, t; }" : "=r"(a) : "l"(p));
    return a;
}
__device__ __forceinline__ void sts128(u32 addr, uint4 v){
    asm volatile("st.shared.v4.b32 [%0], {%1,%2,%3,%4};" :: "r"(addr),
                 "r"(v.x), "r"(v.y), "r"(v.z), "r"(v.w) : "memory");
}
__device__ __forceinline__ void ldsm4(u32* r, u32 addr){
    asm volatile("ldmatrix.sync.aligned.m8n8.x4.shared.b16 {%0,%1,%2,%3}, [%4];"
                 : "=r"(r[0]), "=r"(r[1]), "=r"(r[2]), "=r"(r[3]) : "r"(addr));
}
__device__ __forceinline__ void mma_bf16(float* c, const u32* a, u32 b0, u32 b1){
    asm volatile("mma.sync.aligned.m16n8k16.row.col.f32.bf16.bf16.f32 "
                 "{%0,%1,%2,%3}, {%4,%5,%6,%7}, {%8,%9}, {%0,%1,%2,%3};"
                 : "+f"(c[0]), "+f"(c[1]), "+f"(c[2]), "+f"(c[3])
                 : "r"(a[0]), "r"(a[1]), "r"(a[2]), "r"(a[3]), "r"(b0), "r"(b1));
}

// EPI 0: y=acc*s+b; silu; tanh; out = g*t + bmax       (Wv path, X=img)
// EPI 1: y=acc*s+b; out = silu(y)                      (Wf1, conv Wf2)
// EPI 2: y=acc+b;  out = (1+aw)*img + (1-aw)*y         (Wf3)
template<int EPI, bool SHIFT, int KTOT>
__global__ __launch_bounds__(256, 2) void k_mma(
    const u16* __restrict__ Whi, const u16* __restrict__ Wlo,
    const float* __restrict__ X, float* __restrict__ Y,
    const float* __restrict__ scale, const float* __restrict__ bias,
    const float* __restrict__ img, const float* __restrict__ awp)
{
    __shared__ __align__(16) u16 smarr[24576];   // 48KB
    u32 smb = smem_u32(smarr);

    const int tid = threadIdx.x;
    const int wid = tid >> 5, lane = tid & 31;
    const int warpM = wid >> 1, warpN = wid & 1;
    const int b  = blockIdx.z;
    const int m0 = blockIdx.y*128;
    const int h  = blockIdx.x;               // n0 = h*64
    const float* Xb = X + (size_t)b*C_*HW_;
    float* Yb = Y + (size_t)b*C_*HW_;

    // loader mapping
    const int a_row = tid >> 1, a_half = tid & 1;          // A: 128 rows x two 64B halves
    const int bn_n  = tid >> 2, bn_j0 = (tid & 3)*16;      // B: 64 rows x four 16-k groups

    // ldmatrix role mapping
    const int grp = lane >> 3, idx8 = lane & 7;
    const int aRowL = (grp & 1)*8 + idx8;      // + warpM*32 + mi*16
    const int aKoff = (grp >> 1)*8;
    const int bRowL = (grp >> 1)*8 + idx8;     // + warpN*32 + ni16*16
    const int bKoff = (grp & 1)*8;

    float acc[2][4][4];
    #pragma unroll
    for (int i = 0; i < 2; i++)
        #pragma unroll
        for (int j = 0; j < 4; j++)
            #pragma unroll
            for (int q = 0; q < 4; q++) acc[i][j][q] = 0.f;

    const int NCH = KTOT/64;
    for (int ci = 0; ci < NCH; ci++){
        // ---- global loads into regs ----
        uint4 wh[4], wl[4];
        {
            const uint4* sh = (const uint4*)(Whi + (size_t)(m0+a_row)*KTOT + ci*64 + a_half*32);
            const uint4* sl = (const uint4*)(Wlo + (size_t)(m0+a_row)*KTOT + ci*64 + a_half*32);
            #pragma unroll
            for (int q = 0; q < 4; q++){ wh[q] = sh[q]; wl[q] = sl[q]; }
        }
        u32 hp[8], lp[8];
        {
            int ry = 0, rx = 0, c0;
            if (SHIFT){
                int r = ci >> 2;
                ry = r/3 - 1; rx = r - (r/3)*3 - 1;
                c0 = (ci & 3)*64;
            } else c0 = ci*64;
            int hh = h + ry, ww = bn_n + rx;
            bool ok = !SHIFT || (((unsigned)hh < 64u) && ((unsigned)ww < 64u));
            const float* Xp = Xb + ((size_t)(c0 + bn_j0))*HW_ + hh*64 + ww;
            #pragma unroll
            for (int i = 0; i < 16; i += 2){
                float v0 = ok ? __ldg(Xp + (size_t)i*HW_)     : 0.f;
                float v1 = ok ? __ldg(Xp + (size_t)(i+1)*HW_) : 0.f;
                u16 h0 = f2bf(v0), h1 = f2bf(v1);
                u16 l0 = f2bf(v0 - bf2f(h0));
                u16 l1 = f2bf(v1 - bf2f(h1));
                hp[i>>1] = (u32)h0 | ((u32)h1 << 16);
                lp[i>>1] = (u32)l0 | ((u32)l1 << 16);
            }
        }
        __syncthreads();   // previous compute done reading smem
        // ---- STS (swizzled) ----
        {
            u32 base = a_row*128 + a_half*64;
            #pragma unroll
            for (int q = 0; q < 4; q++){
                u32 kb = (base & 127) + q*16;
                u32 sw = a_row*128 + (kb ^ ((a_row & 7) << 4));
                sts128(smb + OFF_AH + sw, wh[q]);
                sts128(smb + OFF_AL + sw, wl[q]);
            }
            u32 kb = bn_j0*2;
            u32 sw0 = bn_n*128 + ((kb)      ^ ((bn_n & 7) << 4));
            u32 sw1 = bn_n*128 + ((kb + 16) ^ ((bn_n & 7) << 4));
            sts128(smb + OFF_BH + sw0, make_uint4(hp[0],hp[1],hp[2],hp[3]));
            sts128(smb + OFF_BH + sw1, make_uint4(hp[4],hp[5],hp[6],hp[7]));
            sts128(smb + OFF_BL + sw0, make_uint4(lp[0],lp[1],lp[2],lp[3]));
            sts128(smb + OFF_BL + sw1, make_uint4(lp[4],lp[5],lp[6],lp[7]));
        }
        __syncthreads();
        // ---- compute: 4 k16 steps, 24 mma each ----
        #pragma unroll
        for (int k16 = 0; k16 < 4; k16++){
            int kbA = (k16*16 + aKoff)*2;
            int kbB = (k16*16 + bKoff)*2;
            u32 ah[2][4], al[2][4], bh[2][4], bl[2][4];
            #pragma unroll
            for (int mi = 0; mi < 2; mi++){
                int row = warpM*32 + mi*16 + aRowL;
                u32 sw = row*128 + (kbA ^ ((row & 7) << 4));
                ldsm4(ah[mi], smb + OFF_AH + sw);
                ldsm4(al[mi], smb + OFF_AL + sw);
            }
            #pragma unroll
            for (int ni = 0; ni < 2; ni++){
                int row = warpN*32 + ni*16 + bRowL;
                u32 sw = row*128 + (kbB ^ ((row & 7) << 4));
                ldsm4(bh[ni], smb + OFF_BH + sw);
                ldsm4(bl[ni], smb + OFF_BL + sw);
            }
            #pragma unroll
            for (int mi = 0; mi < 2; mi++){
                #pragma unroll
                for (int ni = 0; ni < 2; ni++){
                    // n8 tiles 2*ni (regs 0,1) and 2*ni+1 (regs 2,3)
                    mma_bf16(acc[mi][2*ni],   ah[mi], bh[ni][0], bh[ni][1]);
                    mma_bf16(acc[mi][2*ni],   ah[mi], bl[ni][0], bl[ni][1]);
                    mma_bf16(acc[mi][2*ni],   al[mi], bh[ni][0], bh[ni][1]);
                    mma_bf16(acc[mi][2*ni+1], ah[mi], bh[ni][2], bh[ni][3]);
                    mma_bf16(acc[mi][2*ni+1], ah[mi], bl[ni][2], bl[ni][3]);
                    mma_bf16(acc[mi][2*ni+1], al[mi], bh[ni][2], bh[ni][3]);
                }
            }
        }
    }

    // ---- epilogue ----
    float aw = 0.f;
    if (EPI == 2) aw = tanhf(awp[0]);
    const int r = lane >> 2, cp = (lane & 3)*2;
    #pragma unroll
    for (int mi = 0; mi < 2; mi++){
        int mA = m0 + warpM*32 + mi*16 + r;
        int mB = mA + 8;
        float sA = (EPI == 2) ? 1.f : __ldg(scale + mA);
        float sB = (EPI == 2) ? 1.f : __ldg(scale + mB);
        float bA = __ldg(bias + mA);
        float bB = __ldg(bias + mB);
        #pragma unroll
        for (int j = 0; j < 4; j++){
            int nn = h*64 + warpN*32 + j*8 + cp;
            const float* cc = acc[mi][j];
            float yA0 = fmaf(cc[0], sA, bA), yA1 = fmaf(cc[1], sA, bA);
            float yB0 = fmaf(cc[2], sB, bB), yB1 = fmaf(cc[3], sB, bB);
            float oA0, oA1, oB0, oB1;
            if (EPI == 0){
                float g0 = g_g[(size_t)b*HW_+nn],   g1 = g_g[(size_t)b*HW_+nn+1];
                float x0 = g_bmax[(size_t)b*HW_+nn], x1 = g_bmax[(size_t)b*HW_+nn+1];
                oA0 = fmaf(g0, tanhf(yA0*sigmf(yA0)), x0);
                oA1 = fmaf(g1, tanhf(yA1*sigmf(yA1)), x1);
                oB0 = fmaf(g0, tanhf(yB0*sigmf(yB0)), x0);
                oB1 = fmaf(g1, tanhf(yB1*sigmf(yB1)), x1);
            } else if (EPI == 1){
                oA0 = yA0*sigmf(yA0); oA1 = yA1*sigmf(yA1);
                oB0 = yB0*sigmf(yB0); oB1 = yB1*sigmf(yB1);
            } else {
                float iA0 = img[((size_t)b*C_ + mA)*HW_ + nn];
                float iA1 = img[((size_t)b*C_ + mA)*HW_ + nn + 1];
                float iB0 = img[((size_t)b*C_ + mB)*HW_ + nn];
                float iB1 = img[((size_t)b*C_ + mB)*HW_ + nn + 1];
                oA0 = (1.f+aw)*iA0 + (1.f-aw)*yA0;
                oA1 = (1.f+aw)*iA1 + (1.f-aw)*yA1;
                oB0 = (1.f+aw)*iB0 + (1.f-aw)*yB0;
                oB1 = (1.f+aw)*iB1 + (1.f-aw)*yB1;
            }
            *(float2*)(Yb + (size_t)mA*HW_ + nn) = make_float2(oA0, oA1);
            *(float2*)(Yb + (size_t)mB*HW_ + nn) = make_float2(oB0, oB1);
        }
    }
}

// ---------------- channelwise L2 norm ----------------
__global__ void k_l2norm(const float* __restrict__ X, float* __restrict__ Y)
{
    int q = blockIdx.x*128 + threadIdx.x;
    int b = q >> 12, p = q & 4095;
    const float* xp = X + (size_t)b*C_*HW_ + p;
    float a0 = 0.f, a1 = 0.f, a2 = 0.f, a3 = 0.f;
    #pragma unroll 8
    for (int c = 0; c < C_; c += 4){
        float v0 = xp[(size_t)c*HW_];
        float v1 = xp[(size_t)(c+1)*HW_];
        float v2 = xp[(size_t)(c+2)*HW_];
        float v3 = xp[(size_t)(c+3)*HW_];
        a0 = fmaf(v0, v0, a0); a1 = fmaf(v1, v1, a1);
        a2 = fmaf(v2, v2, a2); a3 = fmaf(v3, v3, a3);
    }
    float n = sqrtf((a0+a1)+(a2+a3));
    float inv = 1.f/fmaxf(n, 1e-12f);
    float* yp = Y + (size_t)b*C_*HW_ + p;
    #pragma unroll 8
    for (int c = 0; c < C_; c++) yp[(size_t)c*HW_] = xp[(size_t)c*HW_]*inv;
}

extern "C" void kernel_launch(void* const* d_in, const int* in_sizes, int n_in,
                              void* d_out, int out_size)
{
    const float* img    = (const float*)d_in[0];
    const float* flang  = (const float*)d_in[1];
    const int*   wmask  = (const int*)  d_in[2];
    const float* sigw   = (const float*)d_in[3];
    const float* W1 = (const float*)d_in[4];  const float* b1 = (const float*)d_in[5];
    const float* W2 = (const float*)d_in[6];  const float* b2 = (const float*)d_in[7];
    const float* Wv = (const float*)d_in[8];  const float* sv = (const float*)d_in[9];  const float* bv = (const float*)d_in[10];
    const float* Wg = (const float*)d_in[11]; const float* sg = (const float*)d_in[12]; const float* bg = (const float*)d_in[13];
    const float* Wb = (const float*)d_in[14]; const float* sb = (const float*)d_in[15]; const float* bb = (const float*)d_in[16];
    const float* Wf1 = (const float*)d_in[17]; const float* sf1 = (const float*)d_in[18]; const float* bf1 = (const float*)d_in[19];
    const float* Wf2 = (const float*)d_in[20]; const float* sf2 = (const float*)d_in[21]; const float* bf2 = (const float*)d_in[22];
    const float* Wf3 = (const float*)d_in[23]; const float* bf3 = (const float*)d_in[24];
    const float* Ws  = (const float*)d_in[25]; const float* bs  = (const float*)d_in[26];
    const float* awp = (const float*)d_in[27];

    float* bufA; cudaGetSymbolAddress((void**)&bufA, g_bufA);
    float* bufB; cudaGetSymbolAddress((void**)&bufB, g_bufB);
    u16* cwh; cudaGetSymbolAddress((void**)&cwh, g_Cwh);
    u16* cwl; cudaGetSymbolAddress((void**)&cwl, g_Cwl);
    u16* parena; cudaGetSymbolAddress((void**)&parena, g_P);
    float* outp = (float*)d_out;

    // small path + weight prep
    k_lang <<<16, 256>>>(flang, wmask, W1, b1, W2, b2);
    k_ssum <<<B_*C_, 128>>>(img);
    k_sigma<<<B_*NC_, 128>>>(Ws, bs, sigw);
    k_gbmax<<<B_*16, 256>>>(Wg, sg, bg, Wb, sb, bb, sigw);
    k_prepW<<<2304, 256>>>(Wf2);
    k_prep1<<<256, 256>>>(Wv, 0);
    k_prep1<<<256, 256>>>(Wf1, 2);
    k_prep1<<<256, 256>>>(Wf3, 4);

    dim3 gm(64, 2, B_);
    const u16* pv_h  = parena;               const u16* pv_l  = parena + 65536;
    const u16* pf1_h = parena + 2*65536;     const u16* pf1_l = parena + 3*65536;
    const u16* pf3_h = parena + 4*65536;     const u16* pf3_l = parena + 5*65536;

    // map_visu + g*t+bmax fused (K=256)
    k_mma<0, false, 256><<<gm, 256>>>(pv_h, pv_l, img, bufA, sv, bv, nullptr, nullptr);
    k_l2norm<<<B_*HW_/128, 128>>>(bufA, bufB);
    // Wf1 cbs (K=256)
    k_mma<1, false, 256><<<gm, 256>>>(pf1_h, pf1_l, bufB, bufA, sf1, bf1, nullptr, nullptr);
    // Wf2 3x3 cbs (K=2304, shifted)
    k_mma<1, true, 2304><<<gm, 256>>>(cwh, cwl, bufA, bufB, sf2, bf2, nullptr, nullptr);
    // Wf3 + residual (K=256)
    k_mma<2, false, 256><<<gm, 256>>>(pf3_h, pf3_l, bufB, bufA, nullptr, bf3, img, awp);
    // final l2norm -> out
    k_l2norm<<<B_*HW_/128, 128>>>(bufA, outp);
}

// round 7
// speedup vs baseline: 2.9595x; 1.5363x over previous
#include <cuda_runtime.h>
#include <cuda_bf16.h>
#include <math.h>

#define B_   16
#define C_   256
#define H_   64
#define HW_  4096
#define L_   40
#define TD_  768
#define EMB_ 392
#define NC_  8

typedef unsigned int u32;
typedef unsigned short u16;

// ---- scratch (no cudaMalloc allowed) ----
__device__ float g_bufA[B_*C_*HW_];                 // f32 NCHW intermediates
// NHWC split-bf16 arenas: [b][pixel][channel]
__device__ __align__(16) u16 g_Ah[B_*HW_*C_];
__device__ __align__(16) u16 g_Al[B_*HW_*C_];
__device__ __align__(16) u16 g_Bh[B_*HW_*C_];
__device__ __align__(16) u16 g_Bl[B_*HW_*C_];
__device__ float g_g[B_*HW_];
__device__ float g_bmax[B_*HW_];
__device__ float g_S[B_*C_*9];
__device__ float g_yc[B_*NC_];
__device__ float g_xc[B_*NC_];
__device__ float g_sy[B_*NC_];
// conv weights, split bf16, k reordered k = r*256 + c
__device__ __align__(16) u16 g_Cwh[256*2304];
__device__ __align__(16) u16 g_Cwl[256*2304];
// 1x1 weights, split bf16
__device__ __align__(16) u16 g_P[6][256*256];

__device__ __forceinline__ float sigmf(float x){ return 1.f/(1.f+expf(-x)); }
__device__ __forceinline__ u16 f2bf(float x){
    __nv_bfloat16 h = __float2bfloat16_rn(x);
    return *reinterpret_cast<u16*>(&h);
}
__device__ __forceinline__ float bf2f(u16 u){
    __nv_bfloat16 h; *reinterpret_cast<u16*>(&h) = u;
    return __bfloat162float(h);
}

// ---------------- K1: language path -> yc/xc ----------------
__global__ void k_lang(const float* __restrict__ flang, const int* __restrict__ wmask,
                       const float* __restrict__ W1, const float* __restrict__ b1,
                       const float* __restrict__ W2, const float* __restrict__ b2)
{
    __shared__ float incs[L_];
    __shared__ float favg[TD_];
    __shared__ float e1s[EMB_];
    __shared__ float mapv[16];
    __shared__ float sinv;
    int b = blockIdx.x, tid = threadIdx.x;
    if (tid == 0){
        float cs[L_]; float c = 0.f;
        for (int l = 0; l < L_; l++){ c += (float)wmask[b*L_+l]; cs[l] = c; }
        float tot = c, s = 0.f;
        for (int l = 0; l < L_; l++){
            float m = (float)wmask[b*L_+l];
            float v = (cs[l] > 1.f && cs[l] < tot) ? m : 0.f;
            incs[l] = v; s += v;
        }
        sinv = 1.f/s;
    }
    __syncthreads();
    for (int d = tid; d < TD_; d += 256){
        float a = 0.f;
        for (int l = 0; l < L_; l++) a += flang[((size_t)b*L_+l)*TD_+d]*incs[l];
        favg[d] = a*sinv;
    }
    __syncthreads();
    for (int j = tid; j < EMB_; j += 256){
        float a = b1[j];
        const float* w = W1 + (size_t)j*TD_;
        for (int d = 0; d < TD_; d++) a = fmaf(favg[d], w[d], a);
        e1s[j] = a;
    }
    __syncthreads();
    if (tid < 16){
        float a = b2[tid];
        const float* w = W2 + (size_t)tid*EMB_;
        for (int j = 0; j < EMB_; j++) a = fmaf(e1s[j], w[j], a);
        mapv[tid] = sigmf(a);
    }
    __syncthreads();
    if (tid < NC_){
        float y = mapv[2*tid]   * (float)H_;
        float x = mapv[2*tid+1] * (float)H_;
        g_yc[b*NC_+tid] = (float)(int)y;
        g_xc[b*NC_+tid] = (float)(int)x;
    }
}

// ---------------- K2: 9 shifted window sums ----------------
__global__ void k_ssum(const float* __restrict__ img)
{
    int bc = blockIdx.x;
    int tid = threadIdx.x;
    const float* p = img + (size_t)bc*HW_;
    float acc[9];
    #pragma unroll
    for (int j = 0; j < 9; j++) acc[j] = 0.f;
    for (int i = tid; i < HW_; i += 128){
        int h = i >> 6, w = i & 63;
        float v = p[i];
        #pragma unroll
        for (int dy = 0; dy < 3; dy++){
            bool oy = (h - dy) >= 0 && (h - dy) <= 61;
            #pragma unroll
            for (int dx = 0; dx < 3; dx++){
                bool ox = (w - dx) >= 0 && (w - dx) <= 61;
                if (oy && ox) acc[dy*3+dx] += v;
            }
        }
    }
    __shared__ float red[9][128];
    #pragma unroll
    for (int j = 0; j < 9; j++) red[j][tid] = acc[j];
    __syncthreads();
    for (int off = 64; off > 0; off >>= 1){
        if (tid < off){
            #pragma unroll
            for (int j = 0; j < 9; j++) red[j][tid] += red[j][tid+off];
        }
        __syncthreads();
    }
    if (tid < 9) g_S[(size_t)bc*9 + tid] = red[tid][0];
}

// ---------------- K3: sigma_y ----------------
__global__ void k_sigma(const float* __restrict__ Ws, const float* __restrict__ bs,
                        const float* __restrict__ sigma_w)
{
    int bn = blockIdx.x; int b = bn >> 3; int nc = bn & 7;
    int tid = threadIdx.x;
    const float* w = Ws  + (size_t)nc*C_*9;
    const float* s = g_S + (size_t)b*C_*9;
    float a = 0.f;
    for (int i = tid; i < C_*9; i += 128) a = fmaf(w[i], s[i], a);
    __shared__ float red[128];
    red[tid] = a; __syncthreads();
    for (int off = 64; off > 0; off >>= 1){
        if (tid < off) red[tid] += red[tid+off];
        __syncthreads();
    }
    if (tid == 0){
        float mean = red[0]*(1.f/3844.f) + bs[nc];
        g_sy[bn] = sigma_w[0]*(float)H_*sigmf(mean);
    }
}

// ---------------- K4: gaussians -> g, bmax ----------------
__global__ void k_gbmax(const float* __restrict__ Wg, const float* __restrict__ sg, const float* __restrict__ bg,
                        const float* __restrict__ Wb, const float* __restrict__ sb, const float* __restrict__ bb,
                        const float* __restrict__ sigma_w)
{
    int blk = blockIdx.x; int b = blk >> 4; int chunk = blk & 15;
    int tid = threadIdx.x;
    __shared__ float syc[8], sxc[8], ssy[8], swg[64], swb[64], ssg[8], sbgs[8], ssb[8], sbbs[8];
    if (tid < 8){
        syc[tid] = g_yc[b*8+tid]; sxc[tid] = g_xc[b*8+tid]; ssy[tid] = g_sy[b*8+tid];
        ssg[tid] = sg[tid]; sbgs[tid] = bg[tid]; ssb[tid] = sb[tid]; sbbs[tid] = bb[tid];
    }
    if (tid < 64){ swg[tid] = Wg[tid]; swb[tid] = Wb[tid]; }
    __syncthreads();
    float sx = sigma_w[0]*(float)H_;
    float inv2sx2 = 1.f/(2.f*sx*sx);
    int p = chunk*256 + tid;
    float fh = (float)(p >> 6), fw = (float)(p & 63);
    float wv[8];
    #pragma unroll
    for (int i = 0; i < 8; i++){
        float dy = fh - syc[i], dx = fw - sxc[i];
        float sy = ssy[i];
        wv[i] = expf(-(dy*dy/(2.f*sy*sy) + dx*dx*inv2sx2));
    }
    float gsum = 0.f, bmx = -1e30f;
    #pragma unroll
    for (int j = 0; j < 8; j++){
        float ag = 0.f, ab = 0.f;
        #pragma unroll
        for (int i = 0; i < 8; i++){
            ag = fmaf(swg[j*8+i], wv[i], ag);
            ab = fmaf(swb[j*8+i], wv[i], ab);
        }
        float yg = fmaf(ag, ssg[j], sbgs[j]);
        gsum += tanhf(yg*sigmf(yg));
        float yb = fmaf(ab, ssb[j], sbbs[j]);
        bmx = fmaxf(bmx, tanhf(yb*sigmf(yb)));
    }
    g_g[(size_t)b*HW_+p]    = gsum*0.125f;
    g_bmax[(size_t)b*HW_+p] = bmx;
}

// ---------------- weight prep ----------------
__global__ void k_prepW(const float* __restrict__ W)
{
    int idx = blockIdx.x*256 + threadIdx.x;
    if (idx >= 256*2304) return;
    int m = idx / 2304;
    int k = idx - m*2304;
    int r = k >> 8;
    int c = k & 255;
    float v = W[(size_t)m*2304 + c*9 + r];
    u16 h = f2bf(v);
    g_Cwh[idx] = h;
    g_Cwl[idx] = f2bf(v - bf2f(h));
}
__global__ void k_prep1(const float* __restrict__ W, int slot)
{
    int idx = blockIdx.x*256 + threadIdx.x;
    if (idx >= 256*256) return;
    float v = W[idx];
    u16 h = f2bf(v);
    g_P[slot][idx]   = h;
    g_P[slot+1][idx] = f2bf(v - bf2f(h));
}

// ---------------- f32 NCHW -> NHWC split bf16 (optionally l2norm first) ----------------
template<bool NORM>
__global__ void k_split(const float* __restrict__ X, u16* __restrict__ Yh, u16* __restrict__ Yl)
{
    int q = blockIdx.x*128 + threadIdx.x;          // q = b*HW + p
    int b = q >> 12, p = q & 4095;
    const float* xp = X + (size_t)b*C_*HW_ + p;
    float inv = 1.f;
    if (NORM){
        float a0 = 0.f, a1 = 0.f, a2 = 0.f, a3 = 0.f;
        #pragma unroll 8
        for (int c = 0; c < C_; c += 4){
            float v0 = xp[(size_t)c*HW_];
            float v1 = xp[(size_t)(c+1)*HW_];
            float v2 = xp[(size_t)(c+2)*HW_];
            float v3 = xp[(size_t)(c+3)*HW_];
            a0 = fmaf(v0, v0, a0); a1 = fmaf(v1, v1, a1);
            a2 = fmaf(v2, v2, a2); a3 = fmaf(v3, v3, a3);
        }
        float n = sqrtf((a0+a1)+(a2+a3));
        inv = 1.f/fmaxf(n, 1e-12f);
    }
    u16* yh = Yh + (size_t)q*C_;
    u16* yl = Yl + (size_t)q*C_;
    #pragma unroll 4
    for (int c = 0; c < C_; c += 8){
        u32 hw[4], lw[4];
        #pragma unroll
        for (int j = 0; j < 8; j += 2){
            float v0 = xp[(size_t)(c+j)*HW_]   * inv;
            float v1 = xp[(size_t)(c+j+1)*HW_] * inv;
            u16 h0 = f2bf(v0), h1 = f2bf(v1);
            u16 l0 = f2bf(v0 - bf2f(h0));
            u16 l1 = f2bf(v1 - bf2f(h1));
            hw[j>>1] = (u32)h0 | ((u32)h1 << 16);
            lw[j>>1] = (u32)l0 | ((u32)l1 << 16);
        }
        *(uint4*)(yh + c) = make_uint4(hw[0], hw[1], hw[2], hw[3]);
        *(uint4*)(yl + c) = make_uint4(lw[0], lw[1], lw[2], lw[3]);
    }
}

// ================== warp-MMA GEMM/conv (mma.sync m16n8k16 bf16, split x3) ==================
// CTA: 256 thr = 8 warps (4x2), tile 128(M) x 64(N = one image row), K chunks of 64.
// A smem: [m][k] K-major 128B rows; B smem: [n][k] K-major 128B rows; both SW swizzled.
// Inputs are NHWC split bf16 -> mainloop has zero conversion ALU, all LDG.128.

#define OFF_AH 0
#define OFF_AL 16384
#define OFF_BH 32768
#define OFF_BL 40960

__device__ __forceinline__ u32 smem_u32(const void* p){
    u32 a;
    asm("{ .reg .u64 t; cvta.to.shared.u64 t, %1; cvt.u32.u64 %0, t; }" : "=r"(a) : "l"(p));
    return a;
}
__device__ __forceinline__ void sts128(u32 addr, uint4 v){
    asm volatile("st.shared.v4.b32 [%0], {%1,%2,%3,%4};" :: "r"(addr),
                 "r"(v.x), "r"(v.y), "r"(v.z), "r"(v.w) : "memory");
}
__device__ __forceinline__ void ldsm4(u32* r, u32 addr){
    asm volatile("ldmatrix.sync.aligned.m8n8.x4.shared.b16 {%0,%1,%2,%3}, [%4];"
                 : "=r"(r[0]), "=r"(r[1]), "=r"(r[2]), "=r"(r[3]) : "r"(addr));
}
__device__ __forceinline__ void mma_bf16(float* c, const u32* a, u32 b0, u32 b1){
    asm volatile("mma.sync.aligned.m16n8k16.row.col.f32.bf16.bf16.f32 "
                 "{%0,%1,%2,%3}, {%4,%5,%6,%7}, {%8,%9}, {%0,%1,%2,%3};"
                 : "+f"(c[0]), "+f"(c[1]), "+f"(c[2]), "+f"(c[3])
                 : "r"(a[0]), "r"(a[1]), "r"(a[2]), "r"(a[3]), "r"(b0), "r"(b1));
}

// EPI 0: y=acc*s+b; silu; tanh; out = g*t + bmax   -> f32 NCHW
// EPI 1: y=acc*s+b; out = silu(y)                  -> NHWC split bf16
// EPI 2: y=acc+b;  out = (1+aw)*img + (1-aw)*y     -> f32 NCHW
template<int EPI, bool SHIFT, int KTOT, bool NHWC_OUT>
__global__ __launch_bounds__(256, 2) void k_mma(
    const u16* __restrict__ Whi, const u16* __restrict__ Wlo,
    const u16* __restrict__ Xh, const u16* __restrict__ Xl,
    float* __restrict__ Yf, u16* __restrict__ Yh, u16* __restrict__ Yl,
    const float* __restrict__ scale, const float* __restrict__ bias,
    const float* __restrict__ img, const float* __restrict__ awp)
{
    __shared__ __align__(16) u16 smarr[24576];   // 48KB
    u32 smb = smem_u32(smarr);

    const int tid = threadIdx.x;
    const int wid = tid >> 5, lane = tid & 31;
    const int warpM = wid >> 1, warpN = wid & 1;
    const int b  = blockIdx.z;
    const int m0 = blockIdx.y*128;
    const int h  = blockIdx.x;               // n0 = h*64

    // loader mapping
    const int a_row = tid >> 1, a_half = tid & 1;   // A: 128 rows x two 64B halves
    const int bn_n  = tid >> 2, bn_part = tid & 3;  // B: 64 pixels x four 16-channel parts

    // ldmatrix role mapping
    const int grp = lane >> 3, idx8 = lane & 7;
    const int aRowL = (grp & 1)*8 + idx8;
    const int aKoff = (grp >> 1)*8;
    const int bRowL = (grp >> 1)*8 + idx8;
    const int bKoff = (grp & 1)*8;

    float acc[2][4][4];
    #pragma unroll
    for (int i = 0; i < 2; i++)
        #pragma unroll
        for (int j = 0; j < 4; j++)
            #pragma unroll
            for (int q = 0; q < 4; q++) acc[i][j][q] = 0.f;

    const int NCH = KTOT/64;
    for (int ci = 0; ci < NCH; ci++){
        // ---- global loads (all LDG.128, pre-split bf16) ----
        uint4 wh[4], wl[4];
        {
            const uint4* sh = (const uint4*)(Whi + (size_t)(m0+a_row)*KTOT + ci*64 + a_half*32);
            const uint4* sl = (const uint4*)(Wlo + (size_t)(m0+a_row)*KTOT + ci*64 + a_half*32);
            #pragma unroll
            for (int q = 0; q < 4; q++){ wh[q] = sh[q]; wl[q] = sl[q]; }
        }
        uint4 bh4[2], bl4[2];
        {
            int ry = 0, rx = 0, c0;
            if (SHIFT){
                int r = ci >> 2;
                ry = r/3 - 1; rx = r - (r/3)*3 - 1;
                c0 = (ci & 3)*64;
            } else c0 = ci*64;
            int hh = h + ry, ww = bn_n + rx;
            bool ok = !SHIFT || (((unsigned)hh < 64u) && ((unsigned)ww < 64u));
            if (ok){
                size_t base = ((size_t)b*HW_ + hh*64 + ww)*C_ + c0 + bn_part*16;
                const uint4* ph = (const uint4*)(Xh + base);
                const uint4* pl = (const uint4*)(Xl + base);
                bh4[0] = ph[0]; bh4[1] = ph[1];
                bl4[0] = pl[0]; bl4[1] = pl[1];
            } else {
                bh4[0] = bh4[1] = bl4[0] = bl4[1] = make_uint4(0,0,0,0);
            }
        }
        __syncthreads();   // previous compute done reading smem
        // ---- STS (swizzled) ----
        {
            #pragma unroll
            for (int q = 0; q < 4; q++){
                u32 kb = a_half*64 + q*16;
                u32 sw = a_row*128 + (kb ^ ((a_row & 7) << 4));
                sts128(smb + OFF_AH + sw, wh[q]);
                sts128(smb + OFF_AL + sw, wl[q]);
            }
            u32 kb = bn_part*32;
            u32 sw0 = bn_n*128 + ((kb)      ^ ((bn_n & 7) << 4));
            u32 sw1 = bn_n*128 + ((kb + 16) ^ ((bn_n & 7) << 4));
            sts128(smb + OFF_BH + sw0, bh4[0]);
            sts128(smb + OFF_BH + sw1, bh4[1]);
            sts128(smb + OFF_BL + sw0, bl4[0]);
            sts128(smb + OFF_BL + sw1, bl4[1]);
        }
        __syncthreads();
        // ---- compute: 4 k16 steps ----
        #pragma unroll
        for (int k16 = 0; k16 < 4; k16++){
            int kbA = (k16*16 + aKoff)*2;
            int kbB = (k16*16 + bKoff)*2;
            u32 ah[2][4], al[2][4], bh[2][4], bl[2][4];
            #pragma unroll
            for (int mi = 0; mi < 2; mi++){
                int row = warpM*32 + mi*16 + aRowL;
                u32 sw = row*128 + (kbA ^ ((row & 7) << 4));
                ldsm4(ah[mi], smb + OFF_AH + sw);
                ldsm4(al[mi], smb + OFF_AL + sw);
            }
            #pragma unroll
            for (int ni = 0; ni < 2; ni++){
                int row = warpN*32 + ni*16 + bRowL;
                u32 sw = row*128 + (kbB ^ ((row & 7) << 4));
                ldsm4(bh[ni], smb + OFF_BH + sw);
                ldsm4(bl[ni], smb + OFF_BL + sw);
            }
            #pragma unroll
            for (int mi = 0; mi < 2; mi++){
                #pragma unroll
                for (int ni = 0; ni < 2; ni++){
                    mma_bf16(acc[mi][2*ni],   ah[mi], bh[ni][0], bh[ni][1]);
                    mma_bf16(acc[mi][2*ni],   ah[mi], bl[ni][0], bl[ni][1]);
                    mma_bf16(acc[mi][2*ni],   al[mi], bh[ni][0], bh[ni][1]);
                    mma_bf16(acc[mi][2*ni+1], ah[mi], bh[ni][2], bh[ni][3]);
                    mma_bf16(acc[mi][2*ni+1], ah[mi], bl[ni][2], bl[ni][3]);
                    mma_bf16(acc[mi][2*ni+1], al[mi], bh[ni][2], bh[ni][3]);
                }
            }
        }
    }

    // ---- epilogue ----
    float aw = 0.f;
    if (EPI == 2) aw = tanhf(awp[0]);
    const int r = lane >> 2, cp = (lane & 3)*2;
    #pragma unroll
    for (int mi = 0; mi < 2; mi++){
        int mA = m0 + warpM*32 + mi*16 + r;
        int mB = mA + 8;
        float sA = (EPI == 2) ? 1.f : __ldg(scale + mA);
        float sB = (EPI == 2) ? 1.f : __ldg(scale + mB);
        float bA = __ldg(bias + mA);
        float bB = __ldg(bias + mB);
        #pragma unroll
        for (int j = 0; j < 4; j++){
            int nn = h*64 + warpN*32 + j*8 + cp;
            const float* cc = acc[mi][j];
            float yA0 = fmaf(cc[0], sA, bA), yA1 = fmaf(cc[1], sA, bA);
            float yB0 = fmaf(cc[2], sB, bB), yB1 = fmaf(cc[3], sB, bB);
            float oA0, oA1, oB0, oB1;
            if (EPI == 0){
                float g0 = g_g[(size_t)b*HW_+nn],   g1 = g_g[(size_t)b*HW_+nn+1];
                float x0 = g_bmax[(size_t)b*HW_+nn], x1 = g_bmax[(size_t)b*HW_+nn+1];
                oA0 = fmaf(g0, tanhf(yA0*sigmf(yA0)), x0);
                oA1 = fmaf(g1, tanhf(yA1*sigmf(yA1)), x1);
                oB0 = fmaf(g0, tanhf(yB0*sigmf(yB0)), x0);
                oB1 = fmaf(g1, tanhf(yB1*sigmf(yB1)), x1);
            } else if (EPI == 1){
                oA0 = yA0*sigmf(yA0); oA1 = yA1*sigmf(yA1);
                oB0 = yB0*sigmf(yB0); oB1 = yB1*sigmf(yB1);
            } else {
                float iA0 = img[((size_t)b*C_ + mA)*HW_ + nn];
                float iA1 = img[((size_t)b*C_ + mA)*HW_ + nn + 1];
                float iB0 = img[((size_t)b*C_ + mB)*HW_ + nn];
                float iB1 = img[((size_t)b*C_ + mB)*HW_ + nn + 1];
                oA0 = (1.f+aw)*iA0 + (1.f-aw)*yA0;
                oA1 = (1.f+aw)*iA1 + (1.f-aw)*yA1;
                oB0 = (1.f+aw)*iB0 + (1.f-aw)*yB0;
                oB1 = (1.f+aw)*iB1 + (1.f-aw)*yB1;
            }
            if (NHWC_OUT){
                size_t r0 = ((size_t)b*HW_ + nn)*C_;
                size_t r1 = ((size_t)b*HW_ + nn + 1)*C_;
                u16 hA0 = f2bf(oA0), hA1 = f2bf(oA1), hB0 = f2bf(oB0), hB1 = f2bf(oB1);
                Yh[r0 + mA] = hA0;  Yl[r0 + mA] = f2bf(oA0 - bf2f(hA0));
                Yh[r1 + mA] = hA1;  Yl[r1 + mA] = f2bf(oA1 - bf2f(hA1));
                Yh[r0 + mB] = hB0;  Yl[r0 + mB] = f2bf(oB0 - bf2f(hB0));
                Yh[r1 + mB] = hB1;  Yl[r1 + mB] = f2bf(oB1 - bf2f(hB1));
            } else {
                float* Yb = Yf + (size_t)b*C_*HW_;
                *(float2*)(Yb + (size_t)mA*HW_ + nn) = make_float2(oA0, oA1);
                *(float2*)(Yb + (size_t)mB*HW_ + nn) = make_float2(oB0, oB1);
            }
        }
    }
}

// ---------------- channelwise L2 norm (f32 -> f32, final) ----------------
__global__ void k_l2norm(const float* __restrict__ X, float* __restrict__ Y)
{
    int q = blockIdx.x*128 + threadIdx.x;
    int b = q >> 12, p = q & 4095;
    const float* xp = X + (size_t)b*C_*HW_ + p;
    float a0 = 0.f, a1 = 0.f, a2 = 0.f, a3 = 0.f;
    #pragma unroll 8
    for (int c = 0; c < C_; c += 4){
        float v0 = xp[(size_t)c*HW_];
        float v1 = xp[(size_t)(c+1)*HW_];
        float v2 = xp[(size_t)(c+2)*HW_];
        float v3 = xp[(size_t)(c+3)*HW_];
        a0 = fmaf(v0, v0, a0); a1 = fmaf(v1, v1, a1);
        a2 = fmaf(v2, v2, a2); a3 = fmaf(v3, v3, a3);
    }
    float n = sqrtf((a0+a1)+(a2+a3));
    float inv = 1.f/fmaxf(n, 1e-12f);
    float* yp = Y + (size_t)b*C_*HW_ + p;
    #pragma unroll 8
    for (int c = 0; c < C_; c++) yp[(size_t)c*HW_] = xp[(size_t)c*HW_]*inv;
}

extern "C" void kernel_launch(void* const* d_in, const int* in_sizes, int n_in,
                              void* d_out, int out_size)
{
    const float* img    = (const float*)d_in[0];
    const float* flang  = (const float*)d_in[1];
    const int*   wmask  = (const int*)  d_in[2];
    const float* sigw   = (const float*)d_in[3];
    const float* W1 = (const float*)d_in[4];  const float* b1 = (const float*)d_in[5];
    const float* W2 = (const float*)d_in[6];  const float* b2 = (const float*)d_in[7];
    const float* Wv = (const float*)d_in[8];  const float* sv = (const float*)d_in[9];  const float* bv = (const float*)d_in[10];
    const float* Wg = (const float*)d_in[11]; const float* sg = (const float*)d_in[12]; const float* bg = (const float*)d_in[13];
    const float* Wb = (const float*)d_in[14]; const float* sb = (const float*)d_in[15]; const float* bb = (const float*)d_in[16];
    const float* Wf1 = (const float*)d_in[17]; const float* sf1 = (const float*)d_in[18]; const float* bf1 = (const float*)d_in[19];
    const float* Wf2 = (const float*)d_in[20]; const float* sf2 = (const float*)d_in[21]; const float* bf2 = (const float*)d_in[22];
    const float* Wf3 = (const float*)d_in[23]; const float* bf3 = (const float*)d_in[24];
    const float* Ws  = (const float*)d_in[25]; const float* bs  = (const float*)d_in[26];
    const float* awp = (const float*)d_in[27];

    float* bufA; cudaGetSymbolAddress((void**)&bufA, g_bufA);
    u16* Ah; cudaGetSymbolAddress((void**)&Ah, g_Ah);
    u16* Al; cudaGetSymbolAddress((void**)&Al, g_Al);
    u16* Bh; cudaGetSymbolAddress((void**)&Bh, g_Bh);
    u16* Bl; cudaGetSymbolAddress((void**)&Bl, g_Bl);
    u16* parena; cudaGetSymbolAddress((void**)&parena, g_P);
    u16* cwh; cudaGetSymbolAddress((void**)&cwh, g_Cwh);
    u16* cwl; cudaGetSymbolAddress((void**)&cwl, g_Cwl);
    float* outp = (float*)d_out;

    // small path + weight prep
    k_lang <<<16, 256>>>(flang, wmask, W1, b1, W2, b2);
    k_ssum <<<B_*C_, 128>>>(img);
    k_sigma<<<B_*NC_, 128>>>(Ws, bs, sigw);
    k_gbmax<<<B_*16, 256>>>(Wg, sg, bg, Wb, sb, bb, sigw);
    k_prepW<<<2304, 256>>>(Wf2);
    k_prep1<<<256, 256>>>(Wv, 0);
    k_prep1<<<256, 256>>>(Wf1, 2);
    k_prep1<<<256, 256>>>(Wf3, 4);

    // img -> NHWC split bf16 (arena A)
    k_split<false><<<B_*HW_/128, 128>>>(img, Ah, Al);

    dim3 gm(64, 2, B_);
    const u16* pv_h  = parena;               const u16* pv_l  = parena + 65536;
    const u16* pf1_h = parena + 2*65536;     const u16* pf1_l = parena + 3*65536;
    const u16* pf3_h = parena + 4*65536;     const u16* pf3_l = parena + 5*65536;

    // map_visu + g*t+bmax fused (K=256): arena A -> bufA f32
    k_mma<0, false, 256, false><<<gm, 256>>>(pv_h, pv_l, Ah, Al, bufA, nullptr, nullptr, sv, bv, nullptr, nullptr);
    // l2norm + split: bufA -> arena B
    k_split<true><<<B_*HW_/128, 128>>>(bufA, Bh, Bl);
    // Wf1 cbs (K=256): arena B -> arena A (NHWC split)
    k_mma<1, false, 256, true><<<gm, 256>>>(pf1_h, pf1_l, Bh, Bl, nullptr, Ah, Al, sf1, bf1, nullptr, nullptr);
    // Wf2 3x3 cbs (K=2304, shifted): arena A -> arena B (NHWC split)
    k_mma<1, true, 2304, true><<<gm, 256>>>(cwh, cwl, Ah, Al, nullptr, Bh, Bl, sf2, bf2, nullptr, nullptr);
    // Wf3 + residual (K=256): arena B -> bufA f32
    k_mma<2, false, 256, false><<<gm, 256>>>(pf3_h, pf3_l, Bh, Bl, bufA, nullptr, nullptr, nullptr, bf3, img, awp);
    // final l2norm -> out
    k_l2norm<<<B_*HW_/128, 128>>>(bufA, outp);
}

// round 8
// speedup vs baseline: 5.1253x; 1.7318x over previous
#include <cuda_runtime.h>
#include <cuda_fp16.h>
#include <math.h>

#define B_   16
#define C_   256
#define H_   64
#define HW_  4096
#define L_   40
#define TD_  768
#define EMB_ 392
#define NC_  8

typedef unsigned int u32;
typedef unsigned short u16;

// ---- scratch (no cudaMalloc allowed) ----
__device__ float g_bufA[B_*C_*HW_];                 // f32 NCHW intermediates
// NHWC fp16 activation arenas: [b][pixel][channel]
__device__ __align__(16) u16 g_Ah[B_*HW_*C_];
__device__ __align__(16) u16 g_Bh[B_*HW_*C_];
__device__ float g_g[B_*HW_];
__device__ float g_bmax[B_*HW_];
__device__ float g_S[B_*C_*9];
__device__ float g_yc[B_*NC_];
__device__ float g_xc[B_*NC_];
__device__ float g_sy[B_*NC_];
// conv weights fp16, k reordered k = r*256 + c
__device__ __align__(16) u16 g_Cwh[256*2304];
// 1x1 weights fp16: [0]=Wv, [1]=Wf1, [2]=Wf3
__device__ __align__(16) u16 g_P[3][256*256];

__device__ __forceinline__ float sigmf(float x){ return 1.f/(1.f+expf(-x)); }
__device__ __forceinline__ u16 f2h(float x){
    __half h = __float2half_rn(x);
    return *reinterpret_cast<u16*>(&h);
}

// ---------------- K1: language path -> yc/xc ----------------
__global__ void k_lang(const float* __restrict__ flang, const int* __restrict__ wmask,
                       const float* __restrict__ W1, const float* __restrict__ b1,
                       const float* __restrict__ W2, const float* __restrict__ b2)
{
    __shared__ float incs[L_];
    __shared__ float favg[TD_];
    __shared__ float e1s[EMB_];
    __shared__ float mapv[16];
    __shared__ float sinv;
    int b = blockIdx.x, tid = threadIdx.x;
    if (tid == 0){
        float cs[L_]; float c = 0.f;
        for (int l = 0; l < L_; l++){ c += (float)wmask[b*L_+l]; cs[l] = c; }
        float tot = c, s = 0.f;
        for (int l = 0; l < L_; l++){
            float m = (float)wmask[b*L_+l];
            float v = (cs[l] > 1.f && cs[l] < tot) ? m : 0.f;
            incs[l] = v; s += v;
        }
        sinv = 1.f/s;
    }
    __syncthreads();
    for (int d = tid; d < TD_; d += 256){
        float a = 0.f;
        for (int l = 0; l < L_; l++) a += flang[((size_t)b*L_+l)*TD_+d]*incs[l];
        favg[d] = a*sinv;
    }
    __syncthreads();
    for (int j = tid; j < EMB_; j += 256){
        float a = b1[j];
        const float* w = W1 + (size_t)j*TD_;
        for (int d = 0; d < TD_; d++) a = fmaf(favg[d], w[d], a);
        e1s[j] = a;
    }
    __syncthreads();
    if (tid < 16){
        float a = b2[tid];
        const float* w = W2 + (size_t)tid*EMB_;
        for (int j = 0; j < EMB_; j++) a = fmaf(e1s[j], w[j], a);
        mapv[tid] = sigmf(a);
    }
    __syncthreads();
    if (tid < NC_){
        float y = mapv[2*tid]   * (float)H_;
        float x = mapv[2*tid+1] * (float)H_;
        g_yc[b*NC_+tid] = (float)(int)y;
        g_xc[b*NC_+tid] = (float)(int)x;
    }
}

// ---------------- K2: 9 shifted window sums ----------------
__global__ void k_ssum(const float* __restrict__ img)
{
    int bc = blockIdx.x;
    int tid = threadIdx.x;
    const float* p = img + (size_t)bc*HW_;
    float acc[9];
    #pragma unroll
    for (int j = 0; j < 9; j++) acc[j] = 0.f;
    for (int i = tid; i < HW_; i += 128){
        int h = i >> 6, w = i & 63;
        float v = p[i];
        #pragma unroll
        for (int dy = 0; dy < 3; dy++){
            bool oy = (h - dy) >= 0 && (h - dy) <= 61;
            #pragma unroll
            for (int dx = 0; dx < 3; dx++){
                bool ox = (w - dx) >= 0 && (w - dx) <= 61;
                if (oy && ox) acc[dy*3+dx] += v;
            }
        }
    }
    __shared__ float red[9][128];
    #pragma unroll
    for (int j = 0; j < 9; j++) red[j][tid] = acc[j];
    __syncthreads();
    for (int off = 64; off > 0; off >>= 1){
        if (tid < off){
            #pragma unroll
            for (int j = 0; j < 9; j++) red[j][tid] += red[j][tid+off];
        }
        __syncthreads();
    }
    if (tid < 9) g_S[(size_t)bc*9 + tid] = red[tid][0];
}

// ---------------- K3: sigma_y ----------------
__global__ void k_sigma(const float* __restrict__ Ws, const float* __restrict__ bs,
                        const float* __restrict__ sigma_w)
{
    int bn = blockIdx.x; int b = bn >> 3; int nc = bn & 7;
    int tid = threadIdx.x;
    const float* w = Ws  + (size_t)nc*C_*9;
    const float* s = g_S + (size_t)b*C_*9;
    float a = 0.f;
    for (int i = tid; i < C_*9; i += 128) a = fmaf(w[i], s[i], a);
    __shared__ float red[128];
    red[tid] = a; __syncthreads();
    for (int off = 64; off > 0; off >>= 1){
        if (tid < off) red[tid] += red[tid+off];
        __syncthreads();
    }
    if (tid == 0){
        float mean = red[0]*(1.f/3844.f) + bs[nc];
        g_sy[bn] = sigma_w[0]*(float)H_*sigmf(mean);
    }
}

// ---------------- K4: gaussians -> g, bmax ----------------
__global__ void k_gbmax(const float* __restrict__ Wg, const float* __restrict__ sg, const float* __restrict__ bg,
                        const float* __restrict__ Wb, const float* __restrict__ sb, const float* __restrict__ bb,
                        const float* __restrict__ sigma_w)
{
    int blk = blockIdx.x; int b = blk >> 4; int chunk = blk & 15;
    int tid = threadIdx.x;
    __shared__ float syc[8], sxc[8], ssy[8], swg[64], swb[64], ssg[8], sbgs[8], ssb[8], sbbs[8];
    if (tid < 8){
        syc[tid] = g_yc[b*8+tid]; sxc[tid] = g_xc[b*8+tid]; ssy[tid] = g_sy[b*8+tid];
        ssg[tid] = sg[tid]; sbgs[tid] = bg[tid]; ssb[tid] = sb[tid]; sbbs[tid] = bb[tid];
    }
    if (tid < 64){ swg[tid] = Wg[tid]; swb[tid] = Wb[tid]; }
    __syncthreads();
    float sx = sigma_w[0]*(float)H_;
    float inv2sx2 = 1.f/(2.f*sx*sx);
    int p = chunk*256 + tid;
    float fh = (float)(p >> 6), fw = (float)(p & 63);
    float wv[8];
    #pragma unroll
    for (int i = 0; i < 8; i++){
        float dy = fh - syc[i], dx = fw - sxc[i];
        float sy = ssy[i];
        wv[i] = expf(-(dy*dy/(2.f*sy*sy) + dx*dx*inv2sx2));
    }
    float gsum = 0.f, bmx = -1e30f;
    #pragma unroll
    for (int j = 0; j < 8; j++){
        float ag = 0.f, ab = 0.f;
        #pragma unroll
        for (int i = 0; i < 8; i++){
            ag = fmaf(swg[j*8+i], wv[i], ag);
            ab = fmaf(swb[j*8+i], wv[i], ab);
        }
        float yg = fmaf(ag, ssg[j], sbgs[j]);
        gsum += tanhf(yg*sigmf(yg));
        float yb = fmaf(ab, ssb[j], sbbs[j]);
        bmx = fmaxf(bmx, tanhf(yb*sigmf(yb)));
    }
    g_g[(size_t)b*HW_+p]    = gsum*0.125f;
    g_bmax[(size_t)b*HW_+p] = bmx;
}

// ---------------- weight prep (fp16) ----------------
__global__ void k_prepW(const float* __restrict__ W)
{
    int idx = blockIdx.x*256 + threadIdx.x;
    if (idx >= 256*2304) return;
    int m = idx / 2304;
    int k = idx - m*2304;
    int r = k >> 8;
    int c = k & 255;
    g_Cwh[idx] = f2h(W[(size_t)m*2304 + c*9 + r]);
}
__global__ void k_prep1(const float* __restrict__ W, int slot)
{
    int idx = blockIdx.x*256 + threadIdx.x;
    if (idx >= 256*256) return;
    g_P[slot][idx] = f2h(W[idx]);
}

// ---------------- f32 NCHW -> NHWC fp16 (optionally l2norm first) ----------------
template<bool NORM>
__global__ void k_split(const float* __restrict__ X, u16* __restrict__ Yh)
{
    int q = blockIdx.x*128 + threadIdx.x;          // q = b*HW + p
    int b = q >> 12, p = q & 4095;
    const float* xp = X + (size_t)b*C_*HW_ + p;
    float inv = 1.f;
    if (NORM){
        float a0 = 0.f, a1 = 0.f, a2 = 0.f, a3 = 0.f;
        #pragma unroll 8
        for (int c = 0; c < C_; c += 4){
            float v0 = xp[(size_t)c*HW_];
            float v1 = xp[(size_t)(c+1)*HW_];
            float v2 = xp[(size_t)(c+2)*HW_];
            float v3 = xp[(size_t)(c+3)*HW_];
            a0 = fmaf(v0, v0, a0); a1 = fmaf(v1, v1, a1);
            a2 = fmaf(v2, v2, a2); a3 = fmaf(v3, v3, a3);
        }
        float n = sqrtf((a0+a1)+(a2+a3));
        inv = 1.f/fmaxf(n, 1e-12f);
    }
    u16* yh = Yh + (size_t)q*C_;
    #pragma unroll 4
    for (int c = 0; c < C_; c += 8){
        u32 hw[4];
        #pragma unroll
        for (int j = 0; j < 8; j += 2){
            float v0 = xp[(size_t)(c+j)*HW_]   * inv;
            float v1 = xp[(size_t)(c+j+1)*HW_] * inv;
            hw[j>>1] = (u32)f2h(v0) | ((u32)f2h(v1) << 16);
        }
        *(uint4*)(yh + c) = make_uint4(hw[0], hw[1], hw[2], hw[3]);
    }
}

// ================== warp-MMA GEMM/conv (mma.sync m16n8k16 fp16, 1-pass) ==================
// CTA: 256 thr = 8 warps (4x2), tile 128(M) x 64(N = one image row), K chunks of 64.
// Double-buffered smem, one __syncthreads per chunk.

#define STG_SZ 12288          // u16 elements per stage: A 8192 (16KB) + B 4096 (8KB)
#define OFF_A(s) ((s)*24576)  // byte offsets into smem
#define OFF_B(s) ((s)*24576 + 16384)

__device__ __forceinline__ u32 smem_u32(const void* p){
    u32 a;
    asm("{ .reg .u64 t; cvta.to.shared.u64 t, %1; cvt.u32.u64 %0, t; }" : "=r"(a) : "l"(p));
    return a;
}
__device__ __forceinline__ void sts128(u32 addr, uint4 v){
    asm volatile("st.shared.v4.b32 [%0], {%1,%2,%3,%4};" :: "r"(addr),
                 "r"(v.x), "r"(v.y), "r"(v.z), "r"(v.w) : "memory");
}
__device__ __forceinline__ void ldsm4(u32* r, u32 addr){
    asm volatile("ldmatrix.sync.aligned.m8n8.x4.shared.b16 {%0,%1,%2,%3}, [%4];"
                 : "=r"(r[0]), "=r"(r[1]), "=r"(r[2]), "=r"(r[3]) : "r"(addr));
}
__device__ __forceinline__ void mma_f16(float* c, const u32* a, u32 b0, u32 b1){
    asm volatile("mma.sync.aligned.m16n8k16.row.col.f32.f16.f16.f32 "
                 "{%0,%1,%2,%3}, {%4,%5,%6,%7}, {%8,%9}, {%0,%1,%2,%3};"
                 : "+f"(c[0]), "+f"(c[1]), "+f"(c[2]), "+f"(c[3])
                 : "r"(a[0]), "r"(a[1]), "r"(a[2]), "r"(a[3]), "r"(b0), "r"(b1));
}

// EPI 0: y=acc*s+b; silu; tanh; out = g*t + bmax   -> f32 NCHW
// EPI 1: y=acc*s+b; out = silu(y)                  -> NHWC fp16
// EPI 2: y=acc+b;  out = (1+aw)*img + (1-aw)*y     -> f32 NCHW
template<int EPI, bool SHIFT, int KTOT, bool NHWC_OUT>
__global__ __launch_bounds__(256, 2) void k_mma(
    const u16* __restrict__ Wh,
    const u16* __restrict__ Xh,
    float* __restrict__ Yf, u16* __restrict__ Yh,
    const float* __restrict__ scale, const float* __restrict__ bias,
    const float* __restrict__ img, const float* __restrict__ awp)
{
    __shared__ __align__(16) u16 smarr[2*STG_SZ];   // 48KB
    u32 smb = smem_u32(smarr);

    const int tid = threadIdx.x;
    const int wid = tid >> 5, lane = tid & 31;
    const int warpM = wid >> 1, warpN = wid & 1;
    const int b  = blockIdx.z;
    const int m0 = blockIdx.y*128;
    const int h  = blockIdx.x;               // n0 = h*64

    // loader mapping
    const int a_row = tid >> 1, a_half = tid & 1;   // A: 128 rows x two 64B halves
    const int bn_n  = tid >> 2, bn_part = tid & 3;  // B: 64 pixels x four 16-channel parts

    // ldmatrix role mapping
    const int grp = lane >> 3, idx8 = lane & 7;
    const int aRowL = (grp & 1)*8 + idx8;
    const int aKoff = (grp >> 1)*8;
    const int bRowL = (grp >> 1)*8 + idx8;
    const int bKoff = (grp & 1)*8;

    float acc[2][4][4];
    #pragma unroll
    for (int i = 0; i < 2; i++)
        #pragma unroll
        for (int j = 0; j < 4; j++)
            #pragma unroll
            for (int q = 0; q < 4; q++) acc[i][j][q] = 0.f;

    const int NCH = KTOT/64;

    // global-load helper values per chunk
    auto loadG = [&](int ci, uint4* wh, uint4* bh4){
        const uint4* sh = (const uint4*)(Wh + (size_t)(m0+a_row)*KTOT + ci*64 + a_half*32);
        #pragma unroll
        for (int q = 0; q < 4; q++) wh[q] = sh[q];
        int ry = 0, rx = 0, c0;
        if (SHIFT){
            int r = ci >> 2;
            ry = r/3 - 1; rx = r - (r/3)*3 - 1;
            c0 = (ci & 3)*64;
        } else c0 = ci*64;
        int hh = h + ry, ww = bn_n + rx;
        bool ok = !SHIFT || (((unsigned)hh < 64u) && ((unsigned)ww < 64u));
        if (ok){
            size_t base = ((size_t)b*HW_ + hh*64 + ww)*C_ + c0 + bn_part*16;
            const uint4* ph = (const uint4*)(Xh + base);
            bh4[0] = ph[0]; bh4[1] = ph[1];
        } else {
            bh4[0] = bh4[1] = make_uint4(0,0,0,0);
        }
    };
    auto stsT = [&](int s, const uint4* wh, const uint4* bh4){
        #pragma unroll
        for (int q = 0; q < 4; q++){
            u32 kb = a_half*64 + q*16;
            u32 sw = a_row*128 + (kb ^ ((a_row & 7) << 4));
            sts128(smb + OFF_A(s) + sw, wh[q]);
        }
        u32 kb = bn_part*32;
        u32 sw0 = bn_n*128 + ((kb)      ^ ((bn_n & 7) << 4));
        u32 sw1 = bn_n*128 + ((kb + 16) ^ ((bn_n & 7) << 4));
        sts128(smb + OFF_B(s) + sw0, bh4[0]);
        sts128(smb + OFF_B(s) + sw1, bh4[1]);
    };

    // prologue: stage 0
    {
        uint4 wh[4], bh4[2];
        loadG(0, wh, bh4);
        stsT(0, wh, bh4);
    }
    __syncthreads();

    for (int ci = 0; ci < NCH; ci++){
        int cur = ci & 1;
        uint4 nwh[4], nbh[2];
        bool more = (ci + 1 < NCH);
        if (more) loadG(ci + 1, nwh, nbh);
        // ---- compute on buffer cur ----
        #pragma unroll
        for (int k16 = 0; k16 < 4; k16++){
            int kbA = (k16*16 + aKoff)*2;
            int kbB = (k16*16 + bKoff)*2;
            u32 ah[2][4], bh[2][4];
            #pragma unroll
            for (int mi = 0; mi < 2; mi++){
                int row = warpM*32 + mi*16 + aRowL;
                u32 sw = row*128 + (kbA ^ ((row & 7) << 4));
                ldsm4(ah[mi], smb + OFF_A(cur) + sw);
            }
            #pragma unroll
            for (int ni = 0; ni < 2; ni++){
                int row = warpN*32 + ni*16 + bRowL;
                u32 sw = row*128 + (kbB ^ ((row & 7) << 4));
                ldsm4(bh[ni], smb + OFF_B(cur) + sw);
            }
            #pragma unroll
            for (int mi = 0; mi < 2; mi++){
                #pragma unroll
                for (int ni = 0; ni < 2; ni++){
                    mma_f16(acc[mi][2*ni],   ah[mi], bh[ni][0], bh[ni][1]);
                    mma_f16(acc[mi][2*ni+1], ah[mi], bh[ni][2], bh[ni][3]);
                }
            }
        }
        if (more) stsT(cur ^ 1, nwh, nbh);
        __syncthreads();
    }

    // ---- epilogue ----
    float aw = 0.f;
    if (EPI == 2) aw = tanhf(awp[0]);
    const int r = lane >> 2, cp = (lane & 3)*2;
    #pragma unroll
    for (int mi = 0; mi < 2; mi++){
        int mA = m0 + warpM*32 + mi*16 + r;
        int mB = mA + 8;
        float sA = (EPI == 2) ? 1.f : __ldg(scale + mA);
        float sB = (EPI == 2) ? 1.f : __ldg(scale + mB);
        float bA = __ldg(bias + mA);
        float bB = __ldg(bias + mB);
        #pragma unroll
        for (int j = 0; j < 4; j++){
            int nn = h*64 + warpN*32 + j*8 + cp;
            const float* cc = acc[mi][j];
            float yA0 = fmaf(cc[0], sA, bA), yA1 = fmaf(cc[1], sA, bA);
            float yB0 = fmaf(cc[2], sB, bB), yB1 = fmaf(cc[3], sB, bB);
            float oA0, oA1, oB0, oB1;
            if (EPI == 0){
                float g0 = g_g[(size_t)b*HW_+nn],   g1 = g_g[(size_t)b*HW_+nn+1];
                float x0 = g_bmax[(size_t)b*HW_+nn], x1 = g_bmax[(size_t)b*HW_+nn+1];
                oA0 = fmaf(g0, tanhf(yA0*sigmf(yA0)), x0);
                oA1 = fmaf(g1, tanhf(yA1*sigmf(yA1)), x1);
                oB0 = fmaf(g0, tanhf(yB0*sigmf(yB0)), x0);
                oB1 = fmaf(g1, tanhf(yB1*sigmf(yB1)), x1);
            } else if (EPI == 1){
                oA0 = yA0*sigmf(yA0); oA1 = yA1*sigmf(yA1);
                oB0 = yB0*sigmf(yB0); oB1 = yB1*sigmf(yB1);
            } else {
                float iA0 = img[((size_t)b*C_ + mA)*HW_ + nn];
                float iA1 = img[((size_t)b*C_ + mA)*HW_ + nn + 1];
                float iB0 = img[((size_t)b*C_ + mB)*HW_ + nn];
                float iB1 = img[((size_t)b*C_ + mB)*HW_ + nn + 1];
                oA0 = (1.f+aw)*iA0 + (1.f-aw)*yA0;
                oA1 = (1.f+aw)*iA1 + (1.f-aw)*yA1;
                oB0 = (1.f+aw)*iB0 + (1.f-aw)*yB0;
                oB1 = (1.f+aw)*iB1 + (1.f-aw)*yB1;
            }
            if (NHWC_OUT){
                size_t r0 = ((size_t)b*HW_ + nn)*C_;
                size_t r1 = ((size_t)b*HW_ + nn + 1)*C_;
                Yh[r0 + mA] = f2h(oA0);
                Yh[r1 + mA] = f2h(oA1);
                Yh[r0 + mB] = f2h(oB0);
                Yh[r1 + mB] = f2h(oB1);
            } else {
                float* Yb = Yf + (size_t)b*C_*HW_;
                *(float2*)(Yb + (size_t)mA*HW_ + nn) = make_float2(oA0, oA1);
                *(float2*)(Yb + (size_t)mB*HW_ + nn) = make_float2(oB0, oB1);
            }
        }
    }
}

// ---------------- channelwise L2 norm (f32 -> f32, final) ----------------
__global__ void k_l2norm(const float* __restrict__ X, float* __restrict__ Y)
{
    int q = blockIdx.x*128 + threadIdx.x;
    int b = q >> 12, p = q & 4095;
    const float* xp = X + (size_t)b*C_*HW_ + p;
    float a0 = 0.f, a1 = 0.f, a2 = 0.f, a3 = 0.f;
    #pragma unroll 8
    for (int c = 0; c < C_; c += 4){
        float v0 = xp[(size_t)c*HW_];
        float v1 = xp[(size_t)(c+1)*HW_];
        float v2 = xp[(size_t)(c+2)*HW_];
        float v3 = xp[(size_t)(c+3)*HW_];
        a0 = fmaf(v0, v0, a0); a1 = fmaf(v1, v1, a1);
        a2 = fmaf(v2, v2, a2); a3 = fmaf(v3, v3, a3);
    }
    float n = sqrtf((a0+a1)+(a2+a3));
    float inv = 1.f/fmaxf(n, 1e-12f);
    float* yp = Y + (size_t)b*C_*HW_ + p;
    #pragma unroll 8
    for (int c = 0; c < C_; c++) yp[(size_t)c*HW_] = xp[(size_t)c*HW_]*inv;
}

extern "C" void kernel_launch(void* const* d_in, const int* in_sizes, int n_in,
                              void* d_out, int out_size)
{
    const float* img    = (const float*)d_in[0];
    const float* flang  = (const float*)d_in[1];
    const int*   wmask  = (const int*)  d_in[2];
    const float* sigw   = (const float*)d_in[3];
    const float* W1 = (const float*)d_in[4];  const float* b1 = (const float*)d_in[5];
    const float* W2 = (const float*)d_in[6];  const float* b2 = (const float*)d_in[7];
    const float* Wv = (const float*)d_in[8];  const float* sv = (const float*)d_in[9];  const float* bv = (const float*)d_in[10];
    const float* Wg = (const float*)d_in[11]; const float* sg = (const float*)d_in[12]; const float* bg = (const float*)d_in[13];
    const float* Wb = (const float*)d_in[14]; const float* sb = (const float*)d_in[15]; const float* bb = (const float*)d_in[16];
    const float* Wf1 = (const float*)d_in[17]; const float* sf1 = (const float*)d_in[18]; const float* bf1 = (const float*)d_in[19];
    const float* Wf2 = (const float*)d_in[20]; const float* sf2 = (const float*)d_in[21]; const float* bf2 = (const float*)d_in[22];
    const float* Wf3 = (const float*)d_in[23]; const float* bf3 = (const float*)d_in[24];
    const float* Ws  = (const float*)d_in[25]; const float* bs  = (const float*)d_in[26];
    const float* awp = (const float*)d_in[27];

    float* bufA; cudaGetSymbolAddress((void**)&bufA, g_bufA);
    u16* Ah; cudaGetSymbolAddress((void**)&Ah, g_Ah);
    u16* Bh; cudaGetSymbolAddress((void**)&Bh, g_Bh);
    u16* parena; cudaGetSymbolAddress((void**)&parena, g_P);
    u16* cwh; cudaGetSymbolAddress((void**)&cwh, g_Cwh);
    float* outp = (float*)d_out;

    // small path + weight prep
    k_lang <<<16, 256>>>(flang, wmask, W1, b1, W2, b2);
    k_ssum <<<B_*C_, 128>>>(img);
    k_sigma<<<B_*NC_, 128>>>(Ws, bs, sigw);
    k_gbmax<<<B_*16, 256>>>(Wg, sg, bg, Wb, sb, bb, sigw);
    k_prepW<<<2304, 256>>>(Wf2);
    k_prep1<<<256, 256>>>(Wv, 0);
    k_prep1<<<256, 256>>>(Wf1, 1);
    k_prep1<<<256, 256>>>(Wf3, 2);

    // img -> NHWC fp16 (arena A)
    k_split<false><<<B_*HW_/128, 128>>>(img, Ah);

    dim3 gm(64, 2, B_);
    const u16* pv  = parena;
    const u16* pf1 = parena + 65536;
    const u16* pf3 = parena + 2*65536;

    // map_visu + g*t+bmax fused (K=256): arena A -> bufA f32
    k_mma<0, false, 256, false><<<gm, 256>>>(pv, Ah, bufA, nullptr, sv, bv, nullptr, nullptr);
    // l2norm + to-fp16: bufA -> arena B
    k_split<true><<<B_*HW_/128, 128>>>(bufA, Bh);
    // Wf1 cbs (K=256): arena B -> arena A (NHWC fp16)
    k_mma<1, false, 256, true><<<gm, 256>>>(pf1, Bh, nullptr, Ah, sf1, bf1, nullptr, nullptr);
    // Wf2 3x3 cbs (K=2304, shifted): arena A -> arena B (NHWC fp16)
    k_mma<1, true, 2304, true><<<gm, 256>>>(cwh, Ah, nullptr, Bh, sf2, bf2, nullptr, nullptr);
    // Wf3 + residual (K=256): arena B -> bufA f32
    k_mma<2, false, 256, false><<<gm, 256>>>(pf3, Bh, bufA, nullptr, nullptr, bf3, img, awp);
    // final l2norm -> out
    k_l2norm<<<B_*HW_/128, 128>>>(bufA, outp);
}